// round 10
// baseline (speedup 1.0000x reference)
#include <cuda_runtime.h>
#include <cuda_fp16.h>
#include <cstdint>
#include <cstddef>

// ---------------------------------------------------------------------------
constexpr int H_  = 96;
constexpr int G_  = 288;
constexpr int T_  = 239;
constexpr int B_  = 4096;
constexpr int NB_ = 32;
constexpr int HW  = 48;    // H/2 packed words per row

constexpr int HP2 = 104;   // fp16 pitch for A (h/x) ldmatrix tiles
constexpr int PW  = 104;   // fp16 pitch for w_ih smem rows

constexpr int KIN  = 512;
constexpr int NFC  = 384;
constexpr int NFCP = 385;
constexpr int KC   = 64;
constexpr int HPf  = 33;

constexpr size_t SZ_X16 = (size_t)T_ * B_ * HW;   // packed fp16 activations
constexpr size_t SZ_H0  = (size_t)B_ * NFC;

__device__ uint32_t g_x16A[SZ_X16];
__device__ uint32_t g_x16B[SZ_X16];
__device__ float    g_h0  [SZ_H0];

// ---------------------------------------------------------------------------
__device__ __forceinline__ float sigf(float x)   { return 1.0f / (1.0f + __expf(-x)); }
__device__ __forceinline__ float tanh_f(float x) { return 2.0f / (1.0f + __expf(-2.0f * x)) - 1.0f; }

__device__ __forceinline__ uint32_t pack_h2(__half a, __half b) {
    return (uint32_t)__half_as_ushort(a) | ((uint32_t)__half_as_ushort(b) << 16);
}
__device__ __forceinline__ void split2h(float x, __half& h, __half& l) {
    h = __float2half_rn(x);
    l = __float2half_rn(x - __half2float(h));
}

__device__ __forceinline__ void mma16816(float c[4], const uint32_t a[4], const uint32_t b[2]) {
    asm volatile(
        "mma.sync.aligned.m16n8k16.row.col.f32.f16.f16.f32 "
        "{%0,%1,%2,%3}, {%4,%5,%6,%7}, {%8,%9}, {%0,%1,%2,%3};"
        : "+f"(c[0]), "+f"(c[1]), "+f"(c[2]), "+f"(c[3])
        : "r"(a[0]), "r"(a[1]), "r"(a[2]), "r"(a[3]), "r"(b[0]), "r"(b[1]));
}
__device__ __forceinline__ void ldsm4(uint32_t r[4], uint32_t addr) {
    asm volatile("ldmatrix.sync.aligned.m8n8.x4.shared.b16 {%0,%1,%2,%3}, [%4];"
                 : "=r"(r[0]), "=r"(r[1]), "=r"(r[2]), "=r"(r[3]) : "r"(addr));
}
__device__ __forceinline__ void cpasync16(uint32_t smem_addr, const void* gptr) {
    asm volatile("cp.async.cg.shared.global [%0], [%1], 16;" :: "r"(smem_addr), "l"(gptr));
}
__device__ __forceinline__ void cpasync_commit() {
    asm volatile("cp.async.commit_group;" ::: "memory");
}
__device__ __forceinline__ void cpasync_wait0() {
    asm volatile("cp.async.wait_group 0;" ::: "memory");
}

// ---------------------------------------------------------------------------
// Fused GRU scan, fp16: A single fp16 (streamed via cp.async), weights 2-term.
// 384 threads = 12 warps; warp w owns j in [8w,8w+8), gate cols +0,+96,+192.
// Intermediate activations live as packed fp16 in gmem. LAST layer writes
// the [B,H,T] output directly (transpose folded in).
// ---------------------------------------------------------------------------
template <bool FUSED, bool LAST>
__global__ void __launch_bounds__(384, 1)
scanF(const float* __restrict__ w_hh, const float* __restrict__ b_hh,
      const float* __restrict__ w_ih, const float* __restrict__ b_ih,
      const float* __restrict__ h0,   const uint32_t* __restrict__ xg,
      uint32_t* __restrict__ outg,    float* __restrict__ outf)
{
    extern __shared__ __align__(16) char smraw[];
    __half* wHi = (__half*)smraw;
    __half* wLo = wHi + (FUSED ? G_ * PW : 0);
    __half* hb  = wLo + (FUSED ? G_ * PW : 0);      // [2 phases][32*HP2]
    __half* xb  = hb + 2 * 32 * HP2;                // [2 phases][32*HP2] (FUSED)
    float* bias_s = (float*)(xb + (FUSED ? 2 * 32 * HP2 : 0));

    const int tid  = threadIdx.x;
    const int lane = tid & 31;
    const int w    = tid >> 5;          // 0..11
    const int b0   = blockIdx.x * NB_;

    // --- w_hh 2-term fp16 fragments in registers ---
    uint32_t bhi[6][3][2], blo[6][3][2];
#pragma unroll
    for (int kt = 0; kt < 6; ++kt)
#pragma unroll
        for (int nt = 0; nt < 3; ++nt) {
            const int g  = nt * 96 + 8 * w + (lane >> 2);
            const int k0 = kt * 16 + (lane & 3) * 2;
            const float* p = w_hh + (size_t)g * H_ + k0;
            float w0 = p[0], w1 = p[1], w2 = p[8], w3 = p[9];
            __half h0b, h1b, h2b, h3b, l0b, l1b, l2b, l3b;
            split2h(w0, h0b, l0b); split2h(w1, h1b, l1b);
            split2h(w2, h2b, l2b); split2h(w3, h3b, l3b);
            bhi[kt][nt][0] = pack_h2(h0b, h1b);
            bhi[kt][nt][1] = pack_h2(h2b, h3b);
            blo[kt][nt][0] = pack_h2(l0b, l1b);
            blo[kt][nt][1] = pack_h2(l2b, l3b);
        }

    // --- w_ih 2-term split into smem (FUSED only) ---
    if constexpr (FUSED) {
        for (int i = tid; i < G_ * H_; i += 384) {
            const int g = i / H_, k = i - g * H_;
            __half h, l; split2h(w_ih[i], h, l);
            wHi[g * PW + k] = h;
            wLo[g * PW + k] = l;
        }
    }
    if (tid < G_) {
        bias_s[tid]      = b_hh[tid];
        bias_s[G_ + tid] = b_ih[tid];
    }

    const int crow = lane >> 2;
    const int jc   = 8 * w + 2 * (lane & 3);

    // --- init h state: registers + single fp16 buffer (phase 0) ---
    float hold[2][4];
#pragma unroll
    for (int mt = 0; mt < 2; ++mt)
#pragma unroll
        for (int rh = 0; rh < 2; ++rh) {
            const int row = mt * 16 + crow + rh * 8;
            const float2 v = *(const float2*)&h0[(size_t)(b0 + row) * H_ + jc];
            hold[mt][rh * 2]     = v.x;
            hold[mt][rh * 2 + 1] = v.y;
            *(uint32_t*)&hb[0 * 32 * HP2 + row * HP2 + jc] =
                pack_h2(__float2half_rn(v.x), __float2half_rn(v.y));
        }

    // --- cp.async mapping: 384 threads = 32 rows x 12 chunks of 16B ---
    const int cprow   = tid / 12;
    const int cpchunk = tid - cprow * 12;
    const uint32_t xbS = (uint32_t)__cvta_generic_to_shared(xb)
                       + (uint32_t)(cprow * HP2 * 2 + cpchunk * 16);
    const uint32_t* xsrc0 = nullptr;
    if constexpr (FUSED) {
        xsrc0 = xg + (size_t)(b0 + cprow) * HW + cpchunk * 4;
        // prologue: x(0) -> xb phase 0
        cpasync16(xbS, xsrc0);
        cpasync_commit();
        cpasync_wait0();
    }
    __syncthreads();

    // ldmatrix per-lane offsets
    const int arow = (lane & 7) + ((lane >> 3) & 1) * 8;
    const int acol = ((lane >> 4) & 1) * 8;
    const uint32_t lofs = (uint32_t)((arow * HP2 + acol) * 2);
    const uint32_t hBase = (uint32_t)__cvta_generic_to_shared(hb) + lofs;
    const uint32_t xBase = (uint32_t)__cvta_generic_to_shared(xb) + lofs;
    constexpr uint32_t BUFB = (uint32_t)(32 * HP2 * 2);

    const int wcol0 = 8 * w + (lane >> 2);
    const int wk0   = (lane & 3) * 2;

    for (int t = 0; t < T_; ++t) {
        const int p  = t & 1;
        const int pn = p ^ 1;

        // stream x(t+1) into xb[pn] (async; waited before end-of-step barrier)
        if constexpr (FUSED) {
            const int tn = (t + 1 < T_) ? (t + 1) : (T_ - 1);
            cpasync16(xbS + (uint32_t)pn * BUFB, xsrc0 + (size_t)tn * B_ * HW);
            cpasync_commit();
        }

        float c[2][3][4];   // r, z, n(hidden)
        float cx[2][4];     // n(input) — separate (stays outside r*(...))
#pragma unroll
        for (int mt = 0; mt < 2; ++mt) {
#pragma unroll
            for (int nt = 0; nt < 3; ++nt)
#pragma unroll
                for (int q = 0; q < 4; ++q) c[mt][nt][q] = 0.f;
#pragma unroll
            for (int q = 0; q < 4; ++q) cx[mt][q] = 0.f;
        }

        const uint32_t aH = hBase + (uint32_t)p * BUFB;
        const uint32_t aX = xBase + (uint32_t)p * BUFB;

#pragma unroll
        for (int kt = 0; kt < 6; ++kt) {
            const uint32_t o = (uint32_t)(kt * 32);
            uint32_t ah0[4], ah1[4];
            ldsm4(ah0, aH + o);
            ldsm4(ah1, aH + o + 16 * HP2 * 2);
#pragma unroll
            for (int nt = 0; nt < 3; ++nt) {
                mma16816(c[0][nt], ah0, bhi[kt][nt]);
                mma16816(c[1][nt], ah1, bhi[kt][nt]);
            }
#pragma unroll
            for (int nt = 0; nt < 3; ++nt) {
                mma16816(c[0][nt], ah0, blo[kt][nt]);
                mma16816(c[1][nt], ah1, blo[kt][nt]);
            }
            if constexpr (FUSED) {
                uint32_t xh0[4], xh1[4];
                ldsm4(xh0, aX + o);
                ldsm4(xh1, aX + o + 16 * HP2 * 2);
                uint32_t bxh[3][2], bxl[3][2];
#pragma unroll
                for (int nt = 0; nt < 3; ++nt) {
                    const int cidx = (nt * 96 + wcol0) * PW + kt * 16 + wk0;
                    bxh[nt][0] = *(const uint32_t*)&wHi[cidx];
                    bxh[nt][1] = *(const uint32_t*)&wHi[cidx + 8];
                    bxl[nt][0] = *(const uint32_t*)&wLo[cidx];
                    bxl[nt][1] = *(const uint32_t*)&wLo[cidx + 8];
                }
                // x GEMM: r,z -> c[][0..1]; n -> cx (separate!)
                mma16816(c[0][0], xh0, bxh[0]);
                mma16816(c[1][0], xh1, bxh[0]);
                mma16816(c[0][1], xh0, bxh[1]);
                mma16816(c[1][1], xh1, bxh[1]);
                mma16816(cx[0],   xh0, bxh[2]);
                mma16816(cx[1],   xh1, bxh[2]);

                mma16816(c[0][0], xh0, bxl[0]);
                mma16816(c[1][0], xh1, bxl[0]);
                mma16816(c[0][1], xh0, bxl[1]);
                mma16816(c[1][1], xh1, bxl[1]);
                mma16816(cx[0],   xh0, bxl[2]);
                mma16816(cx[1],   xh1, bxl[2]);
            }
        }

        float2 bhv[3], biv[3];
#pragma unroll
        for (int g = 0; g < 3; ++g) {
            bhv[g] = *(const float2*)&bias_s[g * 96 + jc];
            biv[g] = *(const float2*)&bias_s[G_ + g * 96 + jc];
        }

#pragma unroll
        for (int mt = 0; mt < 2; ++mt)
#pragma unroll
            for (int rh = 0; rh < 2; ++rh) {
                const int row = mt * 16 + crow + rh * 8;
                float hn2[2];
#pragma unroll
                for (int col = 0; col < 2; ++col) {
                    const int q = rh * 2 + col;
                    const float bhr = (col == 0) ? bhv[0].x : bhv[0].y;
                    const float bhz = (col == 0) ? bhv[1].x : bhv[1].y;
                    const float bhn = (col == 0) ? bhv[2].x : bhv[2].y;
                    const float bir = (col == 0) ? biv[0].x : biv[0].y;
                    const float biz = (col == 0) ? biv[1].x : biv[1].y;
                    const float bin = (col == 0) ? biv[2].x : biv[2].y;
                    const float rg = sigf(bir + c[mt][0][q] + bhr);
                    const float zg = sigf(biz + c[mt][1][q] + bhz);
                    const float ng = tanh_f(bin + cx[mt][q] + rg * (c[mt][2][q] + bhn));
                    const float hv = ng + zg * (hold[mt][q] - ng);
                    hold[mt][q] = hv;
                    hn2[col] = hv;
                }
                const uint32_t ph = pack_h2(__float2half_rn(hn2[0]), __float2half_rn(hn2[1]));
                *(uint32_t*)&hb[pn * 32 * HP2 + row * HP2 + jc] = ph;
                if constexpr (LAST) {
                    const int ob = ((b0 + row) * H_ + jc) * T_ + t;
                    outf[ob]      = hn2[0];
                    outf[ob + T_] = hn2[1];
                } else {
                    outg[(size_t)(t * B_ + b0 + row) * HW + (jc >> 1)] = ph;
                }
            }

        if constexpr (FUSED) cpasync_wait0();
        __syncthreads();
    }
}

// ---------------------------------------------------------------------------
// fc1 (fp32, tiny)
// ---------------------------------------------------------------------------
__global__ void __launch_bounds__(256, 1)
fc1_kernel(const float* __restrict__ z, const float* __restrict__ c,
           const float* __restrict__ w, const float* __restrict__ bias,
           float* __restrict__ h0out)
{
    extern __shared__ float sm[];
    float* wc_s = sm;
    float* xc_s = wc_s + KC * NFCP;

    const int tid = threadIdx.x;
    const int cx  = tid & 31;
    const int ry  = tid >> 5;
    const int b0  = blockIdx.x * NB_;

    float acc[4][12];
#pragma unroll
    for (int m = 0; m < 4; ++m)
#pragma unroll
        for (int i = 0; i < 12; ++i) acc[m][i] = 0.f;

    for (int kc = 0; kc < KIN; kc += KC) {
        for (int idx = tid; idx < NFC * KC; idx += 256) {
            int g = idx / KC, kk = idx - g * KC;
            wc_s[kk * NFCP + g] = w[(size_t)g * KIN + kc + kk];
        }
        for (int idx = tid; idx < NB_ * KC; idx += 256) {
            int r = idx / KC, kk = idx - r * KC;
            int k = kc + kk;
            float v = (k < 256) ? z[(size_t)(b0 + r) * 256 + k]
                                : c[(size_t)(b0 + r) * 256 + (k - 256)];
            xc_s[kk * HPf + r] = v;
        }
        __syncthreads();
#pragma unroll 4
        for (int kk = 0; kk < KC; ++kk) {
            const float a0 = xc_s[kk * HPf + ry +  0];
            const float a1 = xc_s[kk * HPf + ry +  8];
            const float a2 = xc_s[kk * HPf + ry + 16];
            const float a3 = xc_s[kk * HPf + ry + 24];
            const float* wr = wc_s + kk * NFCP + cx;
#pragma unroll
            for (int i = 0; i < 12; ++i) {
                const float wv = wr[32 * i];
                acc[0][i] = fmaf(a0, wv, acc[0][i]);
                acc[1][i] = fmaf(a1, wv, acc[1][i]);
                acc[2][i] = fmaf(a2, wv, acc[2][i]);
                acc[3][i] = fmaf(a3, wv, acc[3][i]);
            }
        }
        __syncthreads();
    }

#pragma unroll
    for (int m = 0; m < 4; ++m) {
        const int r = b0 + ry + 8 * m;
#pragma unroll
        for (int i = 0; i < 12; ++i) {
            const int g = cx + 32 * i;
            float v = acc[m][i] + bias[g];
            v = (v >= 0.f) ? v : 0.2f * v;
            h0out[(size_t)r * NFC + g] = v;
        }
    }
}

// ---------------------------------------------------------------------------
extern "C" void kernel_launch(void* const* d_in, const int* in_sizes, int n_in,
                              void* d_out, int out_size)
{
    const float* z     = (const float*)d_in[0];
    const float* c     = (const float*)d_in[1];
    const float* fc1_w = (const float*)d_in[2];
    const float* fc1_b = (const float*)d_in[3];
    const float* w_ih  = (const float*)d_in[4];
    const float* w_hh  = (const float*)d_in[5];
    const float* b_ih  = (const float*)d_in[6];
    const float* b_hh  = (const float*)d_in[7];
    float* out = (float*)d_out;

    uint32_t *xA, *xB;
    float *h0Buf;
    cudaGetSymbolAddress((void**)&xA,    g_x16A);
    cudaGetSymbolAddress((void**)&xB,    g_x16B);
    cudaGetSymbolAddress((void**)&h0Buf, g_h0);

    const size_t smF = (size_t)(2 * G_ * PW + 4 * 32 * HP2) * sizeof(__half)
                     + (size_t)(2 * G_) * sizeof(float);        // ~148.7 KB
    const size_t sm0 = (size_t)(2 * 32 * HP2) * sizeof(__half)
                     + (size_t)(2 * G_) * sizeof(float);        // ~15.6 KB
    const size_t fcSm = (size_t)(KC * NFCP + KC * HPf) * sizeof(float);

    cudaFuncSetAttribute((const void*)scanF<false, false>, cudaFuncAttributeMaxDynamicSharedMemorySize, (int)sm0);
    cudaFuncSetAttribute((const void*)scanF<true,  false>, cudaFuncAttributeMaxDynamicSharedMemorySize, (int)smF);
    cudaFuncSetAttribute((const void*)scanF<true,  true>,  cudaFuncAttributeMaxDynamicSharedMemorySize, (int)smF);
    cudaFuncSetAttribute((const void*)fc1_kernel,           cudaFuncAttributeMaxDynamicSharedMemorySize, (int)fcSm);

    const int nblk = B_ / NB_;  // 128

    fc1_kernel<<<nblk, 256, fcSm>>>(z, c, fc1_w, fc1_b, h0Buf);

    // layer 0: input zeros -> fp16 activations into xA
    scanF<false, false><<<nblk, 384, sm0>>>(w_hh, b_hh, nullptr, b_ih,
                                            h0Buf, nullptr, xA, nullptr);

    // layer 1: xA -> xB
    scanF<true, false><<<nblk, 384, smF>>>(w_hh + 1 * (size_t)G_ * H_, b_hh + 1 * G_,
                                           w_ih + 1 * (size_t)G_ * H_, b_ih + 1 * G_,
                                           h0Buf + 1 * (size_t)B_ * H_, xA, xB, nullptr);
    // layer 2: xB -> xA
    scanF<true, false><<<nblk, 384, smF>>>(w_hh + 2 * (size_t)G_ * H_, b_hh + 2 * G_,
                                           w_ih + 2 * (size_t)G_ * H_, b_ih + 2 * G_,
                                           h0Buf + 2 * (size_t)B_ * H_, xB, xA, nullptr);
    // layer 3: xA -> out [B,H,T] directly (transpose folded in)
    scanF<true, true><<<nblk, 384, smF>>>(w_hh + 3 * (size_t)G_ * H_, b_hh + 3 * G_,
                                          w_ih + 3 * (size_t)G_ * H_, b_ih + 3 * G_,
                                          h0Buf + 3 * (size_t)B_ * H_, xA, nullptr, out);
}

// round 11
// speedup vs baseline: 1.0329x; 1.0329x over previous
#include <cuda_runtime.h>
#include <cuda_fp16.h>
#include <cstdint>
#include <cstddef>

// ---------------------------------------------------------------------------
constexpr int H_  = 96;
constexpr int G_  = 288;
constexpr int T_  = 239;
constexpr int B_  = 4096;
constexpr int NB_ = 32;
constexpr int HW  = 48;    // H/2 packed words per row

constexpr int HP2 = 104;   // fp16 pitch for A (h/x) ldmatrix tiles

constexpr int KIN  = 512;
constexpr int NFC  = 384;
constexpr int NFCP = 385;
constexpr int KC   = 64;
constexpr int HPf  = 33;

constexpr size_t SZ_X16 = (size_t)T_ * B_ * HW;   // packed fp16 activations
constexpr size_t SZ_H0  = (size_t)B_ * NFC;

__device__ uint32_t g_x16A[SZ_X16];
__device__ uint32_t g_x16B[SZ_X16];
__device__ float    g_h0  [SZ_H0];

// ---------------------------------------------------------------------------
__device__ __forceinline__ float sigf(float x)   { return 1.0f / (1.0f + __expf(-x)); }
__device__ __forceinline__ float tanh_f(float x) { return 2.0f / (1.0f + __expf(-2.0f * x)) - 1.0f; }

__device__ __forceinline__ uint32_t pack_h2(__half a, __half b) {
    return (uint32_t)__half_as_ushort(a) | ((uint32_t)__half_as_ushort(b) << 16);
}
__device__ __forceinline__ void split2h(float x, __half& h, __half& l) {
    h = __float2half_rn(x);
    l = __float2half_rn(x - __half2float(h));
}

__device__ __forceinline__ void mma16816(float c[4], const uint32_t a[4], const uint32_t b0, const uint32_t b1) {
    asm volatile(
        "mma.sync.aligned.m16n8k16.row.col.f32.f16.f16.f32 "
        "{%0,%1,%2,%3}, {%4,%5,%6,%7}, {%8,%9}, {%0,%1,%2,%3};"
        : "+f"(c[0]), "+f"(c[1]), "+f"(c[2]), "+f"(c[3])
        : "r"(a[0]), "r"(a[1]), "r"(a[2]), "r"(a[3]), "r"(b0), "r"(b1));
}
__device__ __forceinline__ void ldsm4(uint32_t r[4], uint32_t addr) {
    asm volatile("ldmatrix.sync.aligned.m8n8.x4.shared.b16 {%0,%1,%2,%3}, [%4];"
                 : "=r"(r[0]), "=r"(r[1]), "=r"(r[2]), "=r"(r[3]) : "r"(addr));
}
__device__ __forceinline__ void cpasync16(uint32_t smem_addr, const void* gptr) {
    asm volatile("cp.async.cg.shared.global [%0], [%1], 16;" :: "r"(smem_addr), "l"(gptr));
}
__device__ __forceinline__ void cpasync_commit() {
    asm volatile("cp.async.commit_group;" ::: "memory");
}
__device__ __forceinline__ void cpasync_wait0() {
    asm volatile("cp.async.wait_group 0;" ::: "memory");
}
__device__ __forceinline__ void cpasync_wait1() {
    asm volatile("cp.async.wait_group 1;" ::: "memory");
}

// x-GEMM phase for one step: zero accumulators, then accumulate x@W_ih^T.
// r,z gates -> c[][0..1]; n gate -> cx (kept separate from r*(...)).
__device__ __forceinline__ void xphase(uint32_t aX, const uint4* __restrict__ wpB,
                                       float c[2][3][4], float cx[2][4])
{
#pragma unroll
    for (int mt = 0; mt < 2; ++mt) {
#pragma unroll
        for (int nt = 0; nt < 3; ++nt)
#pragma unroll
            for (int q = 0; q < 4; ++q) c[mt][nt][q] = 0.f;
#pragma unroll
        for (int q = 0; q < 4; ++q) cx[mt][q] = 0.f;
    }
#pragma unroll
    for (int kt = 0; kt < 6; ++kt) {
        const uint32_t o = (uint32_t)(kt * 32);
        uint32_t xh0[4], xh1[4];
        ldsm4(xh0, aX + o);
        ldsm4(xh1, aX + o + 16 * HP2 * 2);
        uint4 v0 = wpB[(kt * 3 + 0) * 32];
        uint4 v1 = wpB[(kt * 3 + 1) * 32];
        uint4 v2 = wpB[(kt * 3 + 2) * 32];
        // hi terms
        mma16816(c[0][0], xh0, v0.x, v0.y);
        mma16816(c[1][0], xh1, v0.x, v0.y);
        mma16816(c[0][1], xh0, v1.x, v1.y);
        mma16816(c[1][1], xh1, v1.x, v1.y);
        mma16816(cx[0],   xh0, v2.x, v2.y);
        mma16816(cx[1],   xh1, v2.x, v2.y);
        // lo terms
        mma16816(c[0][0], xh0, v0.z, v0.w);
        mma16816(c[1][0], xh1, v0.z, v0.w);
        mma16816(c[0][1], xh0, v1.z, v1.w);
        mma16816(c[1][1], xh1, v1.z, v1.w);
        mma16816(cx[0],   xh0, v2.z, v2.w);
        mma16816(cx[1],   xh1, v2.z, v2.w);
    }
}

// ---------------------------------------------------------------------------
// Fused GRU scan, fp16; x-GEMM hoisted before the barrier (fills phase bubble).
// 384 threads = 12 warps; warp w owns j in [8w,8w+8), gate cols +0,+96,+192.
// ---------------------------------------------------------------------------
template <bool FUSED, bool LAST>
__global__ void __launch_bounds__(384, 1)
scanF(const float* __restrict__ w_hh, const float* __restrict__ b_hh,
      const float* __restrict__ w_ih, const float* __restrict__ b_ih,
      const float* __restrict__ h0,   const uint32_t* __restrict__ xg,
      uint32_t* __restrict__ outg,    float* __restrict__ outf)
{
    extern __shared__ __align__(16) char smraw[];
    // FUSED layout: wp[12][18][32] uint4 | hb[2][32*HP2] | xb[2][32*HP2] | bias[576]
    constexpr int WPW = 12 * 18 * 32;   // uint4 words
    uint4*  wp = (uint4*)smraw;
    __half* hb = (__half*)(smraw + (FUSED ? WPW * 16 : 0));
    __half* xb = hb + 2 * 32 * HP2;
    float* bias_s = (float*)(xb + (FUSED ? 2 * 32 * HP2 : 0));

    const int tid  = threadIdx.x;
    const int lane = tid & 31;
    const int w    = tid >> 5;          // 0..11
    const int b0   = blockIdx.x * NB_;

    // --- w_hh 2-term fp16 fragments in registers ---
    uint32_t bhi[6][3][2], blo[6][3][2];
#pragma unroll
    for (int kt = 0; kt < 6; ++kt)
#pragma unroll
        for (int nt = 0; nt < 3; ++nt) {
            const int g  = nt * 96 + 8 * w + (lane >> 2);
            const int k0 = kt * 16 + (lane & 3) * 2;
            const float* p = w_hh + (size_t)g * H_ + k0;
            float w0 = p[0], w1 = p[1], w2 = p[8], w3 = p[9];
            __half h0b, h1b, h2b, h3b, l0b, l1b, l2b, l3b;
            split2h(w0, h0b, l0b); split2h(w1, h1b, l1b);
            split2h(w2, h2b, l2b); split2h(w3, h3b, l3b);
            bhi[kt][nt][0] = pack_h2(h0b, h1b);
            bhi[kt][nt][1] = pack_h2(h2b, h3b);
            blo[kt][nt][0] = pack_h2(l0b, l1b);
            blo[kt][nt][1] = pack_h2(l2b, l3b);
        }

    // --- w_ih fragments packed per-warp in smem (FUSED only) ---
    if constexpr (FUSED) {
#pragma unroll
        for (int kt = 0; kt < 6; ++kt)
#pragma unroll
            for (int nt = 0; nt < 3; ++nt) {
                const int g  = nt * 96 + 8 * w + (lane >> 2);
                const int k0 = kt * 16 + (lane & 3) * 2;
                const float* p = w_ih + (size_t)g * H_ + k0;
                float w0 = p[0], w1 = p[1], w2 = p[8], w3 = p[9];
                __half h0b, h1b, h2b, h3b, l0b, l1b, l2b, l3b;
                split2h(w0, h0b, l0b); split2h(w1, h1b, l1b);
                split2h(w2, h2b, l2b); split2h(w3, h3b, l3b);
                uint4 v;
                v.x = pack_h2(h0b, h1b);
                v.y = pack_h2(h2b, h3b);
                v.z = pack_h2(l0b, l1b);
                v.w = pack_h2(l2b, l3b);
                wp[((w * 18) + (kt * 3 + nt)) * 32 + lane] = v;
            }
    }
    if (tid < G_) {
        bias_s[tid]      = b_hh[tid];
        bias_s[G_ + tid] = b_ih[tid];
    }

    const int crow = lane >> 2;
    const int jc   = 8 * w + 2 * (lane & 3);

    // --- init h state ---
    float hold[2][4];
#pragma unroll
    for (int mt = 0; mt < 2; ++mt)
#pragma unroll
        for (int rh = 0; rh < 2; ++rh) {
            const int row = mt * 16 + crow + rh * 8;
            const float2 v = *(const float2*)&h0[(size_t)(b0 + row) * H_ + jc];
            hold[mt][rh * 2]     = v.x;
            hold[mt][rh * 2 + 1] = v.y;
            *(uint32_t*)&hb[0 * 32 * HP2 + row * HP2 + jc] =
                pack_h2(__float2half_rn(v.x), __float2half_rn(v.y));
        }

    // --- cp.async mapping: 384 threads = 32 rows x 12 chunks of 16B ---
    const int cprow   = tid / 12;
    const int cpchunk = tid - cprow * 12;
    const uint32_t xbS = (uint32_t)__cvta_generic_to_shared(xb)
                       + (uint32_t)(cprow * HP2 * 2 + cpchunk * 16);
    const uint32_t* xsrc0 = nullptr;
    constexpr uint32_t BUFB = (uint32_t)(32 * HP2 * 2);
    if constexpr (FUSED) {
        xsrc0 = xg + (size_t)(b0 + cprow) * HW + cpchunk * 4;
        cpasync16(xbS, xsrc0);                         // x(0) -> xb[0]
        cpasync_commit();
        cpasync16(xbS + BUFB, xsrc0 + (size_t)B_ * HW); // x(1) -> xb[1]
        cpasync_commit();
        cpasync_wait1();                               // x(0) done
    }
    __syncthreads();

    // ldmatrix per-lane offsets
    const int arow = (lane & 7) + ((lane >> 3) & 1) * 8;
    const int acol = ((lane >> 4) & 1) * 8;
    const uint32_t lofs = (uint32_t)((arow * HP2 + acol) * 2);
    const uint32_t hBase = (uint32_t)__cvta_generic_to_shared(hb) + lofs;
    const uint32_t xBase = (uint32_t)__cvta_generic_to_shared(xb) + lofs;

    const uint4* wpB = wp + (w * 18) * 32 + lane;

    float c[2][3][4];   // r, z, n(hidden)
    float cx[2][4];     // n(input) — separate (stays outside r*(...))

    // prologue: x-GEMM for t=0 (xb[0] visible after the barrier above)
    if constexpr (FUSED) {
        xphase(xBase, wpB, c, cx);
    }

    float2 bhv[3], biv[3];
#pragma unroll
    for (int g = 0; g < 3; ++g) {
        bhv[g] = *(const float2*)&bias_s[g * 96 + jc];
        biv[g] = *(const float2*)&bias_s[G_ + g * 96 + jc];
    }

    for (int t = 0; t < T_; ++t) {
        const int p  = t & 1;
        const int pn = p ^ 1;

        if constexpr (FUSED) {
            cpasync_wait0();    // x(t+1) complete (all threads) ...
        } else {
            // zero accumulators (no x contribution)
#pragma unroll
            for (int mt = 0; mt < 2; ++mt) {
#pragma unroll
                for (int nt = 0; nt < 3; ++nt)
#pragma unroll
                    for (int q = 0; q < 4; ++q) c[mt][nt][q] = 0.f;
#pragma unroll
                for (int q = 0; q < 4; ++q) cx[mt][q] = 0.f;
            }
        }
        __syncthreads();        // ... now visible to all; also protects hb[p]

        // stream x(t+2) into xb[p] (its old content x(t) was consumed last iter)
        if constexpr (FUSED) {
            const int tn2 = (t + 2 < T_) ? (t + 2) : (T_ - 1);
            cpasync16(xbS + (uint32_t)p * BUFB, xsrc0 + (size_t)tn2 * B_ * HW);
            cpasync_commit();
        }

        // h-GEMM for step t
        const uint32_t aH = hBase + (uint32_t)p * BUFB;
#pragma unroll
        for (int kt = 0; kt < 6; ++kt) {
            const uint32_t o = (uint32_t)(kt * 32);
            uint32_t ah0[4], ah1[4];
            ldsm4(ah0, aH + o);
            ldsm4(ah1, aH + o + 16 * HP2 * 2);
#pragma unroll
            for (int nt = 0; nt < 3; ++nt) {
                mma16816(c[0][nt], ah0, bhi[kt][nt][0], bhi[kt][nt][1]);
                mma16816(c[1][nt], ah1, bhi[kt][nt][0], bhi[kt][nt][1]);
            }
#pragma unroll
            for (int nt = 0; nt < 3; ++nt) {
                mma16816(c[0][nt], ah0, blo[kt][nt][0], blo[kt][nt][1]);
                mma16816(c[1][nt], ah1, blo[kt][nt][0], blo[kt][nt][1]);
            }
        }

        // elementwise + h/out stores
#pragma unroll
        for (int mt = 0; mt < 2; ++mt)
#pragma unroll
            for (int rh = 0; rh < 2; ++rh) {
                const int row = mt * 16 + crow + rh * 8;
                float hn2[2];
#pragma unroll
                for (int col = 0; col < 2; ++col) {
                    const int q = rh * 2 + col;
                    const float bhr = (col == 0) ? bhv[0].x : bhv[0].y;
                    const float bhz = (col == 0) ? bhv[1].x : bhv[1].y;
                    const float bhn = (col == 0) ? bhv[2].x : bhv[2].y;
                    const float bir = (col == 0) ? biv[0].x : biv[0].y;
                    const float biz = (col == 0) ? biv[1].x : biv[1].y;
                    const float bin = (col == 0) ? biv[2].x : biv[2].y;
                    const float rg = sigf(bir + c[mt][0][q] + bhr);
                    const float zg = sigf(biz + c[mt][1][q] + bhz);
                    const float ng = tanh_f(bin + cx[mt][q] + rg * (c[mt][2][q] + bhn));
                    const float hv = ng + zg * (hold[mt][q] - ng);
                    hold[mt][q] = hv;
                    hn2[col] = hv;
                }
                const uint32_t ph = pack_h2(__float2half_rn(hn2[0]), __float2half_rn(hn2[1]));
                *(uint32_t*)&hb[pn * 32 * HP2 + row * HP2 + jc] = ph;
                if constexpr (LAST) {
                    const int ob = ((b0 + row) * H_ + jc) * T_ + t;
                    outf[ob]      = hn2[0];
                    outf[ob + T_] = hn2[1];
                } else {
                    outg[(size_t)(t * B_ + b0 + row) * HW + (jc >> 1)] = ph;
                }
            }

        // x-GEMM for step t+1 (independent of h(t+1); fills the pre-barrier gap)
        if constexpr (FUSED) {
            if (t + 1 < T_) {
                xphase(xBase + (uint32_t)pn * BUFB, wpB, c, cx);
            }
        }
    }
}

// ---------------------------------------------------------------------------
// fc1 (fp32, tiny)
// ---------------------------------------------------------------------------
__global__ void __launch_bounds__(256, 1)
fc1_kernel(const float* __restrict__ z, const float* __restrict__ c,
           const float* __restrict__ w, const float* __restrict__ bias,
           float* __restrict__ h0out)
{
    extern __shared__ float sm[];
    float* wc_s = sm;
    float* xc_s = wc_s + KC * NFCP;

    const int tid = threadIdx.x;
    const int cx  = tid & 31;
    const int ry  = tid >> 5;
    const int b0  = blockIdx.x * NB_;

    float acc[4][12];
#pragma unroll
    for (int m = 0; m < 4; ++m)
#pragma unroll
        for (int i = 0; i < 12; ++i) acc[m][i] = 0.f;

    for (int kc = 0; kc < KIN; kc += KC) {
        for (int idx = tid; idx < NFC * KC; idx += 256) {
            int g = idx / KC, kk = idx - g * KC;
            wc_s[kk * NFCP + g] = w[(size_t)g * KIN + kc + kk];
        }
        for (int idx = tid; idx < NB_ * KC; idx += 256) {
            int r = idx / KC, kk = idx - r * KC;
            int k = kc + kk;
            float v = (k < 256) ? z[(size_t)(b0 + r) * 256 + k]
                                : c[(size_t)(b0 + r) * 256 + (k - 256)];
            xc_s[kk * HPf + r] = v;
        }
        __syncthreads();
#pragma unroll 4
        for (int kk = 0; kk < KC; ++kk) {
            const float a0 = xc_s[kk * HPf + ry +  0];
            const float a1 = xc_s[kk * HPf + ry +  8];
            const float a2 = xc_s[kk * HPf + ry + 16];
            const float a3 = xc_s[kk * HPf + ry + 24];
            const float* wr = wc_s + kk * NFCP + cx;
#pragma unroll
            for (int i = 0; i < 12; ++i) {
                const float wv = wr[32 * i];
                acc[0][i] = fmaf(a0, wv, acc[0][i]);
                acc[1][i] = fmaf(a1, wv, acc[1][i]);
                acc[2][i] = fmaf(a2, wv, acc[2][i]);
                acc[3][i] = fmaf(a3, wv, acc[3][i]);
            }
        }
        __syncthreads();
    }

#pragma unroll
    for (int m = 0; m < 4; ++m) {
        const int r = b0 + ry + 8 * m;
#pragma unroll
        for (int i = 0; i < 12; ++i) {
            const int g = cx + 32 * i;
            float v = acc[m][i] + bias[g];
            v = (v >= 0.f) ? v : 0.2f * v;
            h0out[(size_t)r * NFC + g] = v;
        }
    }
}

// ---------------------------------------------------------------------------
extern "C" void kernel_launch(void* const* d_in, const int* in_sizes, int n_in,
                              void* d_out, int out_size)
{
    const float* z     = (const float*)d_in[0];
    const float* c     = (const float*)d_in[1];
    const float* fc1_w = (const float*)d_in[2];
    const float* fc1_b = (const float*)d_in[3];
    const float* w_ih  = (const float*)d_in[4];
    const float* w_hh  = (const float*)d_in[5];
    const float* b_ih  = (const float*)d_in[6];
    const float* b_hh  = (const float*)d_in[7];
    float* out = (float*)d_out;

    uint32_t *xA, *xB;
    float *h0Buf;
    cudaGetSymbolAddress((void**)&xA,    g_x16A);
    cudaGetSymbolAddress((void**)&xB,    g_x16B);
    cudaGetSymbolAddress((void**)&h0Buf, g_h0);

    const size_t smF = (size_t)(12 * 18 * 32) * 16
                     + (size_t)(4 * 32 * HP2) * sizeof(__half)
                     + (size_t)(2 * G_) * sizeof(float);        // 139,520 B
    const size_t sm0 = (size_t)(2 * 32 * HP2) * sizeof(__half)
                     + (size_t)(2 * G_) * sizeof(float);        // ~15.6 KB
    const size_t fcSm = (size_t)(KC * NFCP + KC * HPf) * sizeof(float);

    cudaFuncSetAttribute((const void*)scanF<false, false>, cudaFuncAttributeMaxDynamicSharedMemorySize, (int)sm0);
    cudaFuncSetAttribute((const void*)scanF<true,  false>, cudaFuncAttributeMaxDynamicSharedMemorySize, (int)smF);
    cudaFuncSetAttribute((const void*)scanF<true,  true>,  cudaFuncAttributeMaxDynamicSharedMemorySize, (int)smF);
    cudaFuncSetAttribute((const void*)fc1_kernel,           cudaFuncAttributeMaxDynamicSharedMemorySize, (int)fcSm);

    const int nblk = B_ / NB_;  // 128

    fc1_kernel<<<nblk, 256, fcSm>>>(z, c, fc1_w, fc1_b, h0Buf);

    // layer 0: input zeros -> fp16 activations into xA
    scanF<false, false><<<nblk, 384, sm0>>>(w_hh, b_hh, nullptr, b_ih,
                                            h0Buf, nullptr, xA, nullptr);

    // layer 1: xA -> xB
    scanF<true, false><<<nblk, 384, smF>>>(w_hh + 1 * (size_t)G_ * H_, b_hh + 1 * G_,
                                           w_ih + 1 * (size_t)G_ * H_, b_ih + 1 * G_,
                                           h0Buf + 1 * (size_t)B_ * H_, xA, xB, nullptr);
    // layer 2: xB -> xA
    scanF<true, false><<<nblk, 384, smF>>>(w_hh + 2 * (size_t)G_ * H_, b_hh + 2 * G_,
                                           w_ih + 2 * (size_t)G_ * H_, b_ih + 2 * G_,
                                           h0Buf + 2 * (size_t)B_ * H_, xB, xA, nullptr);
    // layer 3: xA -> out [B,H,T] directly (transpose folded in)
    scanF<true, true><<<nblk, 384, smF>>>(w_hh + 3 * (size_t)G_ * H_, b_hh + 3 * G_,
                                          w_ih + 3 * (size_t)G_ * H_, b_ih + 3 * G_,
                                          h0Buf + 3 * (size_t)B_ * H_, xA, nullptr, out);
}

// round 12
// speedup vs baseline: 1.0734x; 1.0392x over previous
#include <cuda_runtime.h>
#include <cuda_fp16.h>
#include <cstdint>
#include <cstddef>

// ---------------------------------------------------------------------------
constexpr int H_  = 96;
constexpr int G_  = 288;
constexpr int T_  = 239;
constexpr int B_  = 4096;
constexpr int NB_ = 32;
constexpr int HW  = 48;    // H/2 packed words per row

constexpr int HP2 = 104;   // fp16 pitch for A (h/x) ldmatrix tiles
constexpr int THR = 768;   // 24 warps: 12 j-groups x 2 m-groups

constexpr int KIN  = 512;
constexpr int NFC  = 384;
constexpr int NFCP = 385;
constexpr int KC   = 64;
constexpr int HPf  = 33;

constexpr size_t SZ_X16 = (size_t)T_ * B_ * HW;   // packed fp16 activations
constexpr size_t SZ_H0  = (size_t)B_ * NFC;

__device__ uint32_t g_x16A[SZ_X16];
__device__ uint32_t g_x16B[SZ_X16];
__device__ float    g_h0  [SZ_H0];

// ---------------------------------------------------------------------------
__device__ __forceinline__ float sigf(float x)   { return 1.0f / (1.0f + __expf(-x)); }
__device__ __forceinline__ float tanh_f(float x) { return 2.0f / (1.0f + __expf(-2.0f * x)) - 1.0f; }

__device__ __forceinline__ uint32_t pack_h2(__half a, __half b) {
    return (uint32_t)__half_as_ushort(a) | ((uint32_t)__half_as_ushort(b) << 16);
}
__device__ __forceinline__ void split2h(float x, __half& h, __half& l) {
    h = __float2half_rn(x);
    l = __float2half_rn(x - __half2float(h));
}

__device__ __forceinline__ void mma16816(float c[4], const uint32_t a[4], const uint32_t b0, const uint32_t b1) {
    asm volatile(
        "mma.sync.aligned.m16n8k16.row.col.f32.f16.f16.f32 "
        "{%0,%1,%2,%3}, {%4,%5,%6,%7}, {%8,%9}, {%0,%1,%2,%3};"
        : "+f"(c[0]), "+f"(c[1]), "+f"(c[2]), "+f"(c[3])
        : "r"(a[0]), "r"(a[1]), "r"(a[2]), "r"(a[3]), "r"(b0), "r"(b1));
}
__device__ __forceinline__ void ldsm4(uint32_t r[4], uint32_t addr) {
    asm volatile("ldmatrix.sync.aligned.m8n8.x4.shared.b16 {%0,%1,%2,%3}, [%4];"
                 : "=r"(r[0]), "=r"(r[1]), "=r"(r[2]), "=r"(r[3]) : "r"(addr));
}
__device__ __forceinline__ void cpasync16(uint32_t smem_addr, const void* gptr) {
    asm volatile("cp.async.cg.shared.global [%0], [%1], 16;" :: "r"(smem_addr), "l"(gptr));
}
__device__ __forceinline__ void cpasync_commit() {
    asm volatile("cp.async.commit_group;" ::: "memory");
}
__device__ __forceinline__ void cpasync_wait0() {
    asm volatile("cp.async.wait_group 0;" ::: "memory");
}
__device__ __forceinline__ void cpasync_wait1() {
    asm volatile("cp.async.wait_group 1;" ::: "memory");
}

// ---------------------------------------------------------------------------
// Fused GRU scan, 24 warps (m-split). Warp = (mg, wj): m-rows [16mg,16mg+16),
// j-cols [8wj, 8wj+8), gate cols at +0,+96,+192.
// w_hh hi in regs; w_hh lo + w_ih (hi,lo) packed in smem.
// n-gate input term accumulated separately (cx) — stays outside r*(...).
// ---------------------------------------------------------------------------
template <bool FUSED, bool LAST>
__global__ void __launch_bounds__(THR, 1)
scanF(const float* __restrict__ w_hh, const float* __restrict__ b_hh,
      const float* __restrict__ w_ih, const float* __restrict__ b_ih,
      const float* __restrict__ h0,   const uint32_t* __restrict__ xg,
      uint32_t* __restrict__ outg,    float* __restrict__ outf)
{
    extern __shared__ __align__(16) char smraw[];
    // layout: wpIh[12*18*32] uint4 (FUSED) | wpLo[12*18*32] uint2 |
    //         hb[2][32*HP2] | xb[2][32*HP2] (FUSED) | bias[576]
    constexpr int NFR = 12 * 18 * 32;
    uint4*  wpIh = (uint4*)smraw;
    uint2*  wpLo = (uint2*)(smraw + (FUSED ? NFR * 16 : 0));
    __half* hb   = (__half*)((char*)wpLo + NFR * 8);
    __half* xb   = hb + 2 * 32 * HP2;
    float* bias_s = (float*)(xb + (FUSED ? 2 * 32 * HP2 : 0));

    const int tid  = threadIdx.x;
    const int lane = tid & 31;
    const int w    = tid >> 5;          // 0..23
    const int wj   = w % 12;            // j-group
    const int mg   = w / 12;            // m-group (0: rows 0-15, 1: rows 16-31)
    const int b0   = blockIdx.x * NB_;

    // --- w_hh: hi fragments -> regs; lo fragments -> smem (mg 0 writes) ---
    uint32_t bhi[6][3][2];
#pragma unroll
    for (int kt = 0; kt < 6; ++kt)
#pragma unroll
        for (int nt = 0; nt < 3; ++nt) {
            const int g  = nt * 96 + 8 * wj + (lane >> 2);
            const int k0 = kt * 16 + (lane & 3) * 2;
            const float* p = w_hh + (size_t)g * H_ + k0;
            float w0 = p[0], w1 = p[1], w2 = p[8], w3 = p[9];
            __half h0b, h1b, h2b, h3b, l0b, l1b, l2b, l3b;
            split2h(w0, h0b, l0b); split2h(w1, h1b, l1b);
            split2h(w2, h2b, l2b); split2h(w3, h3b, l3b);
            bhi[kt][nt][0] = pack_h2(h0b, h1b);
            bhi[kt][nt][1] = pack_h2(h2b, h3b);
            if (mg == 0) {
                uint2 lv;
                lv.x = pack_h2(l0b, l1b);
                lv.y = pack_h2(l2b, l3b);
                wpLo[(wj * 18 + kt * 3 + nt) * 32 + lane] = lv;
            }
        }

    // --- w_ih fragments packed in smem (FUSED; mg 0 writes) ---
    if constexpr (FUSED) {
        if (mg == 0) {
#pragma unroll
            for (int kt = 0; kt < 6; ++kt)
#pragma unroll
                for (int nt = 0; nt < 3; ++nt) {
                    const int g  = nt * 96 + 8 * wj + (lane >> 2);
                    const int k0 = kt * 16 + (lane & 3) * 2;
                    const float* p = w_ih + (size_t)g * H_ + k0;
                    float w0 = p[0], w1 = p[1], w2 = p[8], w3 = p[9];
                    __half h0b, h1b, h2b, h3b, l0b, l1b, l2b, l3b;
                    split2h(w0, h0b, l0b); split2h(w1, h1b, l1b);
                    split2h(w2, h2b, l2b); split2h(w3, h3b, l3b);
                    uint4 v;
                    v.x = pack_h2(h0b, h1b);
                    v.y = pack_h2(h2b, h3b);
                    v.z = pack_h2(l0b, l1b);
                    v.w = pack_h2(l2b, l3b);
                    wpIh[(wj * 18 + kt * 3 + nt) * 32 + lane] = v;
                }
        }
    }
    if (tid < G_) {
        bias_s[tid]      = b_hh[tid];
        bias_s[G_ + tid] = b_ih[tid];
    }

    const int crow = lane >> 2;
    const int jc   = 8 * wj + 2 * (lane & 3);
    const int rbase = mg * 16 + crow;     // + rh*8

    // --- init h state (this warp's 16 rows only) ---
    float hold[4];   // [rh*2+col]
#pragma unroll
    for (int rh = 0; rh < 2; ++rh) {
        const int row = rbase + rh * 8;
        const float2 v = *(const float2*)&h0[(size_t)(b0 + row) * H_ + jc];
        hold[rh * 2]     = v.x;
        hold[rh * 2 + 1] = v.y;
        *(uint32_t*)&hb[0 * 32 * HP2 + row * HP2 + jc] =
            pack_h2(__float2half_rn(v.x), __float2half_rn(v.y));
    }

    // --- cp.async mapping: 384 slots = 32 rows x 12 chunks of 16B ---
    const bool cpon   = (tid < 384);
    const int cprow   = tid / 12;
    const int cpchunk = tid - cprow * 12;
    const uint32_t xbS = (uint32_t)__cvta_generic_to_shared(xb)
                       + (uint32_t)(cprow * HP2 * 2 + cpchunk * 16);
    const uint32_t* xsrc0 = nullptr;
    constexpr uint32_t BUFB = (uint32_t)(32 * HP2 * 2);
    if constexpr (FUSED) {
        if (cpon) {
            xsrc0 = xg + (size_t)(b0 + cprow) * HW + cpchunk * 4;
            cpasync16(xbS, xsrc0);                          // x(0) -> xb[0]
            cpasync_commit();
            cpasync16(xbS + BUFB, xsrc0 + (size_t)B_ * HW); // x(1) -> xb[1]
            cpasync_commit();
            cpasync_wait1();                                // x(0) done
        }
    }
    __syncthreads();

    // ldmatrix per-lane offsets (16-row tile of this m-group)
    const int arow = (lane & 7) + ((lane >> 3) & 1) * 8;
    const int acol = ((lane >> 4) & 1) * 8;
    const uint32_t lofs = (uint32_t)(((mg * 16 + arow) * HP2 + acol) * 2);
    const uint32_t hBase = (uint32_t)__cvta_generic_to_shared(hb) + lofs;
    const uint32_t xBase = (uint32_t)__cvta_generic_to_shared(xb) + lofs;

    const uint4* wpIhB = wpIh + (wj * 18) * 32 + lane;
    const uint2* wpLoB = wpLo + (wj * 18) * 32 + lane;

    float c[3][4];   // r, z, n(hidden)
    float cx[4];     // n(input) — separate (stays outside r*(...))

    // prologue: x-GEMM for t=0
    if constexpr (FUSED) {
#pragma unroll
        for (int nt = 0; nt < 3; ++nt)
#pragma unroll
            for (int q = 0; q < 4; ++q) c[nt][q] = 0.f;
#pragma unroll
        for (int q = 0; q < 4; ++q) cx[q] = 0.f;
#pragma unroll
        for (int kt = 0; kt < 6; ++kt) {
            uint32_t xh[4];
            ldsm4(xh, xBase + (uint32_t)(kt * 32));
            uint4 v0 = wpIhB[(kt * 3 + 0) * 32];
            uint4 v1 = wpIhB[(kt * 3 + 1) * 32];
            uint4 v2 = wpIhB[(kt * 3 + 2) * 32];
            mma16816(c[0], xh, v0.x, v0.y);
            mma16816(c[1], xh, v1.x, v1.y);
            mma16816(cx,   xh, v2.x, v2.y);
            mma16816(c[0], xh, v0.z, v0.w);
            mma16816(c[1], xh, v1.z, v1.w);
            mma16816(cx,   xh, v2.z, v2.w);
        }
    }

    for (int t = 0; t < T_; ++t) {
        const int p  = t & 1;
        const int pn = p ^ 1;

        if constexpr (FUSED) {
            if (cpon) cpasync_wait0();   // x(t+1) complete
        } else {
#pragma unroll
            for (int nt = 0; nt < 3; ++nt)
#pragma unroll
                for (int q = 0; q < 4; ++q) c[nt][q] = 0.f;
#pragma unroll
            for (int q = 0; q < 4; ++q) cx[q] = 0.f;
        }
        __syncthreads();    // x(t+1)/h(t) visible; protects hb/xb[p]

        // stream x(t+2) into xb[p]
        if constexpr (FUSED) {
            if (cpon) {
                const int tn2 = (t + 2 < T_) ? (t + 2) : (T_ - 1);
                cpasync16(xbS + (uint32_t)p * BUFB, xsrc0 + (size_t)tn2 * B_ * HW);
                cpasync_commit();
            }
        }

        // h-GEMM for step t (hi from regs, lo from smem)
        const uint32_t aH = hBase + (uint32_t)p * BUFB;
#pragma unroll
        for (int kt = 0; kt < 6; ++kt) {
            uint32_t ah[4];
            ldsm4(ah, aH + (uint32_t)(kt * 32));
            mma16816(c[0], ah, bhi[kt][0][0], bhi[kt][0][1]);
            mma16816(c[1], ah, bhi[kt][1][0], bhi[kt][1][1]);
            mma16816(c[2], ah, bhi[kt][2][0], bhi[kt][2][1]);
            uint2 l0 = wpLoB[(kt * 3 + 0) * 32];
            uint2 l1 = wpLoB[(kt * 3 + 1) * 32];
            uint2 l2 = wpLoB[(kt * 3 + 2) * 32];
            mma16816(c[0], ah, l0.x, l0.y);
            mma16816(c[1], ah, l1.x, l1.y);
            mma16816(c[2], ah, l2.x, l2.y);
        }

        // elementwise + stores (4 elements per thread)
        const float2 bh0 = *(const float2*)&bias_s[0 * 96 + jc];
        const float2 bh1 = *(const float2*)&bias_s[1 * 96 + jc];
        const float2 bh2 = *(const float2*)&bias_s[2 * 96 + jc];
        const float2 bi0 = *(const float2*)&bias_s[G_ + 0 * 96 + jc];
        const float2 bi1 = *(const float2*)&bias_s[G_ + 1 * 96 + jc];
        const float2 bi2 = *(const float2*)&bias_s[G_ + 2 * 96 + jc];
#pragma unroll
        for (int rh = 0; rh < 2; ++rh) {
            const int row = rbase + rh * 8;
            float hn2[2];
#pragma unroll
            for (int col = 0; col < 2; ++col) {
                const int q = rh * 2 + col;
                const float bhr = (col == 0) ? bh0.x : bh0.y;
                const float bhz = (col == 0) ? bh1.x : bh1.y;
                const float bhn = (col == 0) ? bh2.x : bh2.y;
                const float bir = (col == 0) ? bi0.x : bi0.y;
                const float biz = (col == 0) ? bi1.x : bi1.y;
                const float bin = (col == 0) ? bi2.x : bi2.y;
                const float rg = sigf(bir + c[0][q] + bhr);
                const float zg = sigf(biz + c[1][q] + bhz);
                const float ng = tanh_f(bin + cx[q] + rg * (c[2][q] + bhn));
                const float hv = ng + zg * (hold[q] - ng);
                hold[q] = hv;
                hn2[col] = hv;
            }
            const uint32_t ph = pack_h2(__float2half_rn(hn2[0]), __float2half_rn(hn2[1]));
            *(uint32_t*)&hb[pn * 32 * HP2 + row * HP2 + jc] = ph;
            if constexpr (LAST) {
                const int ob = ((b0 + row) * H_ + jc) * T_ + t;
                outf[ob]      = hn2[0];
                outf[ob + T_] = hn2[1];
            } else {
                outg[(size_t)(t * B_ + b0 + row) * HW + (jc >> 1)] = ph;
            }
        }

        // x-GEMM for step t+1 (fills the pre-barrier gap)
        if constexpr (FUSED) {
            if (t + 1 < T_) {
                const uint32_t aX = xBase + (uint32_t)pn * BUFB;
#pragma unroll
                for (int nt = 0; nt < 3; ++nt)
#pragma unroll
                    for (int q = 0; q < 4; ++q) c[nt][q] = 0.f;
#pragma unroll
                for (int q = 0; q < 4; ++q) cx[q] = 0.f;
#pragma unroll
                for (int kt = 0; kt < 6; ++kt) {
                    uint32_t xh[4];
                    ldsm4(xh, aX + (uint32_t)(kt * 32));
                    uint4 v0 = wpIhB[(kt * 3 + 0) * 32];
                    uint4 v1 = wpIhB[(kt * 3 + 1) * 32];
                    uint4 v2 = wpIhB[(kt * 3 + 2) * 32];
                    mma16816(c[0], xh, v0.x, v0.y);
                    mma16816(c[1], xh, v1.x, v1.y);
                    mma16816(cx,   xh, v2.x, v2.y);
                    mma16816(c[0], xh, v0.z, v0.w);
                    mma16816(c[1], xh, v1.z, v1.w);
                    mma16816(cx,   xh, v2.z, v2.w);
                }
            }
        }
    }
}

// ---------------------------------------------------------------------------
// fc1 (fp32, tiny)
// ---------------------------------------------------------------------------
__global__ void __launch_bounds__(256, 1)
fc1_kernel(const float* __restrict__ z, const float* __restrict__ c,
           const float* __restrict__ w, const float* __restrict__ bias,
           float* __restrict__ h0out)
{
    extern __shared__ float sm[];
    float* wc_s = sm;
    float* xc_s = wc_s + KC * NFCP;

    const int tid = threadIdx.x;
    const int cx  = tid & 31;
    const int ry  = tid >> 5;
    const int b0  = blockIdx.x * NB_;

    float acc[4][12];
#pragma unroll
    for (int m = 0; m < 4; ++m)
#pragma unroll
        for (int i = 0; i < 12; ++i) acc[m][i] = 0.f;

    for (int kc = 0; kc < KIN; kc += KC) {
        for (int idx = tid; idx < NFC * KC; idx += 256) {
            int g = idx / KC, kk = idx - g * KC;
            wc_s[kk * NFCP + g] = w[(size_t)g * KIN + kc + kk];
        }
        for (int idx = tid; idx < NB_ * KC; idx += 256) {
            int r = idx / KC, kk = idx - r * KC;
            int k = kc + kk;
            float v = (k < 256) ? z[(size_t)(b0 + r) * 256 + k]
                                : c[(size_t)(b0 + r) * 256 + (k - 256)];
            xc_s[kk * HPf + r] = v;
        }
        __syncthreads();
#pragma unroll 4
        for (int kk = 0; kk < KC; ++kk) {
            const float a0 = xc_s[kk * HPf + ry +  0];
            const float a1 = xc_s[kk * HPf + ry +  8];
            const float a2 = xc_s[kk * HPf + ry + 16];
            const float a3 = xc_s[kk * HPf + ry + 24];
            const float* wr = wc_s + kk * NFCP + cx;
#pragma unroll
            for (int i = 0; i < 12; ++i) {
                const float wv = wr[32 * i];
                acc[0][i] = fmaf(a0, wv, acc[0][i]);
                acc[1][i] = fmaf(a1, wv, acc[1][i]);
                acc[2][i] = fmaf(a2, wv, acc[2][i]);
                acc[3][i] = fmaf(a3, wv, acc[3][i]);
            }
        }
        __syncthreads();
    }

#pragma unroll
    for (int m = 0; m < 4; ++m) {
        const int r = b0 + ry + 8 * m;
#pragma unroll
        for (int i = 0; i < 12; ++i) {
            const int g = cx + 32 * i;
            float v = acc[m][i] + bias[g];
            v = (v >= 0.f) ? v : 0.2f * v;
            h0out[(size_t)r * NFC + g] = v;
        }
    }
}

// ---------------------------------------------------------------------------
extern "C" void kernel_launch(void* const* d_in, const int* in_sizes, int n_in,
                              void* d_out, int out_size)
{
    const float* z     = (const float*)d_in[0];
    const float* c     = (const float*)d_in[1];
    const float* fc1_w = (const float*)d_in[2];
    const float* fc1_b = (const float*)d_in[3];
    const float* w_ih  = (const float*)d_in[4];
    const float* w_hh  = (const float*)d_in[5];
    const float* b_ih  = (const float*)d_in[6];
    const float* b_hh  = (const float*)d_in[7];
    float* out = (float*)d_out;

    uint32_t *xA, *xB;
    float *h0Buf;
    cudaGetSymbolAddress((void**)&xA,    g_x16A);
    cudaGetSymbolAddress((void**)&xB,    g_x16B);
    cudaGetSymbolAddress((void**)&h0Buf, g_h0);

    constexpr int NFR = 12 * 18 * 32;
    const size_t smF = (size_t)NFR * 16 + (size_t)NFR * 8
                     + (size_t)(4 * 32 * HP2) * sizeof(__half)
                     + (size_t)(2 * G_) * sizeof(float);        // 194,816 B
    const size_t sm0 = (size_t)NFR * 8
                     + (size_t)(2 * 32 * HP2) * sizeof(__half)
                     + (size_t)(2 * G_) * sizeof(float);        // 70,912 B
    const size_t fcSm = (size_t)(KC * NFCP + KC * HPf) * sizeof(float);

    cudaFuncSetAttribute((const void*)scanF<false, false>, cudaFuncAttributeMaxDynamicSharedMemorySize, (int)sm0);
    cudaFuncSetAttribute((const void*)scanF<true,  false>, cudaFuncAttributeMaxDynamicSharedMemorySize, (int)smF);
    cudaFuncSetAttribute((const void*)scanF<true,  true>,  cudaFuncAttributeMaxDynamicSharedMemorySize, (int)smF);
    cudaFuncSetAttribute((const void*)fc1_kernel,           cudaFuncAttributeMaxDynamicSharedMemorySize, (int)fcSm);

    const int nblk = B_ / NB_;  // 128

    fc1_kernel<<<nblk, 256, fcSm>>>(z, c, fc1_w, fc1_b, h0Buf);

    // layer 0: input zeros -> fp16 activations into xA
    scanF<false, false><<<nblk, THR, sm0>>>(w_hh, b_hh, nullptr, b_ih,
                                            h0Buf, nullptr, xA, nullptr);

    // layer 1: xA -> xB
    scanF<true, false><<<nblk, THR, smF>>>(w_hh + 1 * (size_t)G_ * H_, b_hh + 1 * G_,
                                           w_ih + 1 * (size_t)G_ * H_, b_ih + 1 * G_,
                                           h0Buf + 1 * (size_t)B_ * H_, xA, xB, nullptr);
    // layer 2: xB -> xA
    scanF<true, false><<<nblk, THR, smF>>>(w_hh + 2 * (size_t)G_ * H_, b_hh + 2 * G_,
                                           w_ih + 2 * (size_t)G_ * H_, b_ih + 2 * G_,
                                           h0Buf + 2 * (size_t)B_ * H_, xB, xA, nullptr);
    // layer 3: xA -> out [B,H,T] directly (transpose folded in)
    scanF<true, true><<<nblk, THR, smF>>>(w_hh + 3 * (size_t)G_ * H_, b_hh + 3 * G_,
                                          w_ih + 3 * (size_t)G_ * H_, b_ih + 3 * G_,
                                          h0Buf + 3 * (size_t)B_ * H_, xA, nullptr, out);
}

// round 13
// speedup vs baseline: 1.1468x; 1.0684x over previous
#include <cuda_runtime.h>
#include <cuda_fp16.h>
#include <cstdint>
#include <cstddef>

// ---------------------------------------------------------------------------
constexpr int H_  = 96;
constexpr int G_  = 288;
constexpr int T_  = 239;
constexpr int B_  = 4096;
constexpr int NB_ = 32;
constexpr int HW  = 48;    // H/2 packed words per row

constexpr int HP2 = 104;   // fp16 pitch for A (h/x) ldmatrix tiles
constexpr int THR = 768;   // 24 warps: 12 j-groups x 2 m-groups

constexpr int KIN  = 512;
constexpr int NFC  = 384;
constexpr int NFCP = 385;
constexpr int KC   = 64;
constexpr int HPf  = 33;

constexpr size_t SZ_X16 = (size_t)T_ * B_ * HW;   // packed fp16 activations
constexpr size_t SZ_H0  = (size_t)B_ * NFC;

__device__ uint32_t g_x16A[SZ_X16];
__device__ uint32_t g_x16B[SZ_X16];
__device__ float    g_h0  [SZ_H0];

// ---------------------------------------------------------------------------
__device__ __forceinline__ float sigf(float x)   { return 1.0f / (1.0f + __expf(-x)); }
__device__ __forceinline__ float tanh_f(float x) { return 2.0f / (1.0f + __expf(-2.0f * x)) - 1.0f; }

__device__ __forceinline__ uint32_t pack_h2(__half a, __half b) {
    return (uint32_t)__half_as_ushort(a) | ((uint32_t)__half_as_ushort(b) << 16);
}
__device__ __forceinline__ void split2h(float x, __half& h, __half& l) {
    h = __float2half_rn(x);
    l = __float2half_rn(x - __half2float(h));
}

__device__ __forceinline__ void mma16816(float c[4], const uint32_t a[4], const uint32_t b0, const uint32_t b1) {
    asm volatile(
        "mma.sync.aligned.m16n8k16.row.col.f32.f16.f16.f32 "
        "{%0,%1,%2,%3}, {%4,%5,%6,%7}, {%8,%9}, {%0,%1,%2,%3};"
        : "+f"(c[0]), "+f"(c[1]), "+f"(c[2]), "+f"(c[3])
        : "r"(a[0]), "r"(a[1]), "r"(a[2]), "r"(a[3]), "r"(b0), "r"(b1));
}
__device__ __forceinline__ void ldsm4(uint32_t r[4], uint32_t addr) {
    asm volatile("ldmatrix.sync.aligned.m8n8.x4.shared.b16 {%0,%1,%2,%3}, [%4];"
                 : "=r"(r[0]), "=r"(r[1]), "=r"(r[2]), "=r"(r[3]) : "r"(addr));
}
__device__ __forceinline__ void cpasync16(uint32_t smem_addr, const void* gptr) {
    asm volatile("cp.async.cg.shared.global [%0], [%1], 16;" :: "r"(smem_addr), "l"(gptr));
}
__device__ __forceinline__ void cpasync_commit() {
    asm volatile("cp.async.commit_group;" ::: "memory");
}
__device__ __forceinline__ void cpasync_wait0() {
    asm volatile("cp.async.wait_group 0;" ::: "memory");
}
__device__ __forceinline__ void cpasync_wait1() {
    asm volatile("cp.async.wait_group 1;" ::: "memory");
}

// ---------------------------------------------------------------------------
// Fused GRU scan, 24 warps (m-split). Warp = (mg, wj): m-rows [16mg,16mg+16),
// j-cols [8wj, 8wj+8), gate cols at +0,+96,+192.
// h-GEMM: 2-term fp16 weights (hi regs, lo smem when FUSED / regs when not).
// x-GEMM: SINGLE-term fp16 weights (hi only, smem) — precision budget trade.
// n-gate input term accumulated separately (cx) — stays outside r*(...).
// ---------------------------------------------------------------------------
template <bool FUSED, bool LAST>
__global__ void __launch_bounds__(THR, 1)
scanF(const float* __restrict__ w_hh, const float* __restrict__ b_hh,
      const float* __restrict__ w_ih, const float* __restrict__ b_ih,
      const float* __restrict__ h0,   const uint32_t* __restrict__ xg,
      uint32_t* __restrict__ outg,    float* __restrict__ outf)
{
    extern __shared__ __align__(16) char smraw[];
    // layout: wpIh[12*18*32] uint2 (FUSED) | wpLo[12*18*32] uint2 (FUSED) |
    //         hb[2][32*HP2] | xb[2][32*HP2] (FUSED) | bias[576]
    constexpr int NFR = 12 * 18 * 32;
    uint2*  wpIh = (uint2*)smraw;
    uint2*  wpLo = (uint2*)(smraw + (FUSED ? NFR * 8 : 0));
    __half* hb   = (__half*)((char*)wpLo + (FUSED ? NFR * 8 : 0));
    __half* xb   = hb + 2 * 32 * HP2;
    float* bias_s = (float*)(xb + (FUSED ? 2 * 32 * HP2 : 0));

    const int tid  = threadIdx.x;
    const int lane = tid & 31;
    const int w    = tid >> 5;          // 0..23
    const int wj   = w % 12;            // j-group
    const int mg   = w / 12;            // m-group (0: rows 0-15, 1: rows 16-31)
    const int b0   = blockIdx.x * NB_;

    // --- w_hh: hi fragments -> regs; lo -> smem (FUSED) or regs (!FUSED) ---
    uint32_t bhi[6][3][2];
    uint32_t bloR[6][3][2];   // used only when !FUSED (dead-stripped otherwise)
#pragma unroll
    for (int kt = 0; kt < 6; ++kt)
#pragma unroll
        for (int nt = 0; nt < 3; ++nt) {
            const int g  = nt * 96 + 8 * wj + (lane >> 2);
            const int k0 = kt * 16 + (lane & 3) * 2;
            const float* p = w_hh + (size_t)g * H_ + k0;
            float w0 = p[0], w1 = p[1], w2 = p[8], w3 = p[9];
            __half h0b, h1b, h2b, h3b, l0b, l1b, l2b, l3b;
            split2h(w0, h0b, l0b); split2h(w1, h1b, l1b);
            split2h(w2, h2b, l2b); split2h(w3, h3b, l3b);
            bhi[kt][nt][0] = pack_h2(h0b, h1b);
            bhi[kt][nt][1] = pack_h2(h2b, h3b);
            if constexpr (FUSED) {
                if (mg == 0) {
                    uint2 lv;
                    lv.x = pack_h2(l0b, l1b);
                    lv.y = pack_h2(l2b, l3b);
                    wpLo[(wj * 18 + kt * 3 + nt) * 32 + lane] = lv;
                }
            } else {
                bloR[kt][nt][0] = pack_h2(l0b, l1b);
                bloR[kt][nt][1] = pack_h2(l2b, l3b);
            }
        }

    // --- w_ih hi-only fragments in smem (FUSED; mg 0 writes) ---
    if constexpr (FUSED) {
        if (mg == 0) {
#pragma unroll
            for (int kt = 0; kt < 6; ++kt)
#pragma unroll
                for (int nt = 0; nt < 3; ++nt) {
                    const int g  = nt * 96 + 8 * wj + (lane >> 2);
                    const int k0 = kt * 16 + (lane & 3) * 2;
                    const float* p = w_ih + (size_t)g * H_ + k0;
                    uint2 v;
                    v.x = pack_h2(__float2half_rn(p[0]), __float2half_rn(p[1]));
                    v.y = pack_h2(__float2half_rn(p[8]), __float2half_rn(p[9]));
                    wpIh[(wj * 18 + kt * 3 + nt) * 32 + lane] = v;
                }
        }
    }
    if (tid < G_) {
        bias_s[tid]      = b_hh[tid];
        bias_s[G_ + tid] = b_ih[tid];
    }

    const int crow = lane >> 2;
    const int jc   = 8 * wj + 2 * (lane & 3);
    const int rbase = mg * 16 + crow;     // + rh*8

    // --- init h state (this warp's 16 rows only) ---
    float hold[4];   // [rh*2+col]
#pragma unroll
    for (int rh = 0; rh < 2; ++rh) {
        const int row = rbase + rh * 8;
        const float2 v = *(const float2*)&h0[(size_t)(b0 + row) * H_ + jc];
        hold[rh * 2]     = v.x;
        hold[rh * 2 + 1] = v.y;
        *(uint32_t*)&hb[0 * 32 * HP2 + row * HP2 + jc] =
            pack_h2(__float2half_rn(v.x), __float2half_rn(v.y));
    }

    // --- cp.async mapping: 384 slots = 32 rows x 12 chunks of 16B ---
    const bool cpon   = (tid < 384);
    const int cprow   = tid / 12;
    const int cpchunk = tid - cprow * 12;
    const uint32_t xbS = (uint32_t)__cvta_generic_to_shared(xb)
                       + (uint32_t)(cprow * HP2 * 2 + cpchunk * 16);
    const uint32_t* xsrc0 = nullptr;
    constexpr uint32_t BUFB = (uint32_t)(32 * HP2 * 2);
    if constexpr (FUSED) {
        if (cpon) {
            xsrc0 = xg + (size_t)(b0 + cprow) * HW + cpchunk * 4;
            cpasync16(xbS, xsrc0);                          // x(0) -> xb[0]
            cpasync_commit();
            cpasync16(xbS + BUFB, xsrc0 + (size_t)B_ * HW); // x(1) -> xb[1]
            cpasync_commit();
            cpasync_wait1();                                // x(0) done
        }
    }
    __syncthreads();

    // ldmatrix per-lane offsets (16-row tile of this m-group)
    const int arow = (lane & 7) + ((lane >> 3) & 1) * 8;
    const int acol = ((lane >> 4) & 1) * 8;
    const uint32_t lofs = (uint32_t)(((mg * 16 + arow) * HP2 + acol) * 2);
    const uint32_t hBase = (uint32_t)__cvta_generic_to_shared(hb) + lofs;
    const uint32_t xBase = (uint32_t)__cvta_generic_to_shared(xb) + lofs;

    const uint2* wpIhB = wpIh + (wj * 18) * 32 + lane;
    const uint2* wpLoB = wpLo + (wj * 18) * 32 + lane;

    float c[3][4];   // r, z, n(hidden)
    float cx[4];     // n(input) — separate (stays outside r*(...))

    // prologue: x-GEMM for t=0 (hi-only weights)
    if constexpr (FUSED) {
#pragma unroll
        for (int nt = 0; nt < 3; ++nt)
#pragma unroll
            for (int q = 0; q < 4; ++q) c[nt][q] = 0.f;
#pragma unroll
        for (int q = 0; q < 4; ++q) cx[q] = 0.f;
#pragma unroll
        for (int kt = 0; kt < 6; ++kt) {
            uint32_t xh[4];
            ldsm4(xh, xBase + (uint32_t)(kt * 32));
            uint2 v0 = wpIhB[(kt * 3 + 0) * 32];
            uint2 v1 = wpIhB[(kt * 3 + 1) * 32];
            uint2 v2 = wpIhB[(kt * 3 + 2) * 32];
            mma16816(c[0], xh, v0.x, v0.y);
            mma16816(c[1], xh, v1.x, v1.y);
            mma16816(cx,   xh, v2.x, v2.y);
        }
    }

    for (int t = 0; t < T_; ++t) {
        const int p  = t & 1;
        const int pn = p ^ 1;

        if constexpr (FUSED) {
            if (cpon) cpasync_wait0();   // x(t+1) complete
        } else {
#pragma unroll
            for (int nt = 0; nt < 3; ++nt)
#pragma unroll
                for (int q = 0; q < 4; ++q) c[nt][q] = 0.f;
#pragma unroll
            for (int q = 0; q < 4; ++q) cx[q] = 0.f;
        }
        __syncthreads();    // x(t+1)/h(t) visible; protects hb/xb[p]

        // stream x(t+2) into xb[p]
        if constexpr (FUSED) {
            if (cpon) {
                const int tn2 = (t + 2 < T_) ? (t + 2) : (T_ - 1);
                cpasync16(xbS + (uint32_t)p * BUFB, xsrc0 + (size_t)tn2 * B_ * HW);
                cpasync_commit();
            }
        }

        // h-GEMM for step t (hi regs; lo from smem when FUSED, regs otherwise)
        const uint32_t aH = hBase + (uint32_t)p * BUFB;
#pragma unroll
        for (int kt = 0; kt < 6; ++kt) {
            uint32_t ah[4];
            ldsm4(ah, aH + (uint32_t)(kt * 32));
            mma16816(c[0], ah, bhi[kt][0][0], bhi[kt][0][1]);
            mma16816(c[1], ah, bhi[kt][1][0], bhi[kt][1][1]);
            mma16816(c[2], ah, bhi[kt][2][0], bhi[kt][2][1]);
            if constexpr (FUSED) {
                uint2 l0 = wpLoB[(kt * 3 + 0) * 32];
                uint2 l1 = wpLoB[(kt * 3 + 1) * 32];
                uint2 l2 = wpLoB[(kt * 3 + 2) * 32];
                mma16816(c[0], ah, l0.x, l0.y);
                mma16816(c[1], ah, l1.x, l1.y);
                mma16816(c[2], ah, l2.x, l2.y);
            } else {
                mma16816(c[0], ah, bloR[kt][0][0], bloR[kt][0][1]);
                mma16816(c[1], ah, bloR[kt][1][0], bloR[kt][1][1]);
                mma16816(c[2], ah, bloR[kt][2][0], bloR[kt][2][1]);
            }
        }

        // elementwise + stores (4 elements per thread)
        const float2 bh0 = *(const float2*)&bias_s[0 * 96 + jc];
        const float2 bh1 = *(const float2*)&bias_s[1 * 96 + jc];
        const float2 bh2 = *(const float2*)&bias_s[2 * 96 + jc];
        const float2 bi0 = *(const float2*)&bias_s[G_ + 0 * 96 + jc];
        const float2 bi1 = *(const float2*)&bias_s[G_ + 1 * 96 + jc];
        const float2 bi2 = *(const float2*)&bias_s[G_ + 2 * 96 + jc];
#pragma unroll
        for (int rh = 0; rh < 2; ++rh) {
            const int row = rbase + rh * 8;
            float hn2[2];
#pragma unroll
            for (int col = 0; col < 2; ++col) {
                const int q = rh * 2 + col;
                const float bhr = (col == 0) ? bh0.x : bh0.y;
                const float bhz = (col == 0) ? bh1.x : bh1.y;
                const float bhn = (col == 0) ? bh2.x : bh2.y;
                const float bir = (col == 0) ? bi0.x : bi0.y;
                const float biz = (col == 0) ? bi1.x : bi1.y;
                const float bin = (col == 0) ? bi2.x : bi2.y;
                const float rg = sigf(bir + c[0][q] + bhr);
                const float zg = sigf(biz + c[1][q] + bhz);
                const float ng = tanh_f(bin + cx[q] + rg * (c[2][q] + bhn));
                const float hv = ng + zg * (hold[q] - ng);
                hold[q] = hv;
                hn2[col] = hv;
            }
            const uint32_t ph = pack_h2(__float2half_rn(hn2[0]), __float2half_rn(hn2[1]));
            *(uint32_t*)&hb[pn * 32 * HP2 + row * HP2 + jc] = ph;
            if constexpr (LAST) {
                const int ob = ((b0 + row) * H_ + jc) * T_ + t;
                outf[ob]      = hn2[0];
                outf[ob + T_] = hn2[1];
            } else {
                outg[(size_t)(t * B_ + b0 + row) * HW + (jc >> 1)] = ph;
            }
        }

        // x-GEMM for step t+1 (hi-only; fills the pre-barrier gap)
        if constexpr (FUSED) {
            if (t + 1 < T_) {
                const uint32_t aX = xBase + (uint32_t)pn * BUFB;
#pragma unroll
                for (int nt = 0; nt < 3; ++nt)
#pragma unroll
                    for (int q = 0; q < 4; ++q) c[nt][q] = 0.f;
#pragma unroll
                for (int q = 0; q < 4; ++q) cx[q] = 0.f;
#pragma unroll
                for (int kt = 0; kt < 6; ++kt) {
                    uint32_t xh[4];
                    ldsm4(xh, aX + (uint32_t)(kt * 32));
                    uint2 v0 = wpIhB[(kt * 3 + 0) * 32];
                    uint2 v1 = wpIhB[(kt * 3 + 1) * 32];
                    uint2 v2 = wpIhB[(kt * 3 + 2) * 32];
                    mma16816(c[0], xh, v0.x, v0.y);
                    mma16816(c[1], xh, v1.x, v1.y);
                    mma16816(cx,   xh, v2.x, v2.y);
                }
            }
        }
    }
}

// ---------------------------------------------------------------------------
// fc1 (fp32, tiny)
// ---------------------------------------------------------------------------
__global__ void __launch_bounds__(256, 1)
fc1_kernel(const float* __restrict__ z, const float* __restrict__ c,
           const float* __restrict__ w, const float* __restrict__ bias,
           float* __restrict__ h0out)
{
    extern __shared__ float sm[];
    float* wc_s = sm;
    float* xc_s = wc_s + KC * NFCP;

    const int tid = threadIdx.x;
    const int cx  = tid & 31;
    const int ry  = tid >> 5;
    const int b0  = blockIdx.x * NB_;

    float acc[4][12];
#pragma unroll
    for (int m = 0; m < 4; ++m)
#pragma unroll
        for (int i = 0; i < 12; ++i) acc[m][i] = 0.f;

    for (int kc = 0; kc < KIN; kc += KC) {
        for (int idx = tid; idx < NFC * KC; idx += 256) {
            int g = idx / KC, kk = idx - g * KC;
            wc_s[kk * NFCP + g] = w[(size_t)g * KIN + kc + kk];
        }
        for (int idx = tid; idx < NB_ * KC; idx += 256) {
            int r = idx / KC, kk = idx - r * KC;
            int k = kc + kk;
            float v = (k < 256) ? z[(size_t)(b0 + r) * 256 + k]
                                : c[(size_t)(b0 + r) * 256 + (k - 256)];
            xc_s[kk * HPf + r] = v;
        }
        __syncthreads();
#pragma unroll 4
        for (int kk = 0; kk < KC; ++kk) {
            const float a0 = xc_s[kk * HPf + ry +  0];
            const float a1 = xc_s[kk * HPf + ry +  8];
            const float a2 = xc_s[kk * HPf + ry + 16];
            const float a3 = xc_s[kk * HPf + ry + 24];
            const float* wr = wc_s + kk * NFCP + cx;
#pragma unroll
            for (int i = 0; i < 12; ++i) {
                const float wv = wr[32 * i];
                acc[0][i] = fmaf(a0, wv, acc[0][i]);
                acc[1][i] = fmaf(a1, wv, acc[1][i]);
                acc[2][i] = fmaf(a2, wv, acc[2][i]);
                acc[3][i] = fmaf(a3, wv, acc[3][i]);
            }
        }
        __syncthreads();
    }

#pragma unroll
    for (int m = 0; m < 4; ++m) {
        const int r = b0 + ry + 8 * m;
#pragma unroll
        for (int i = 0; i < 12; ++i) {
            const int g = cx + 32 * i;
            float v = acc[m][i] + bias[g];
            v = (v >= 0.f) ? v : 0.2f * v;
            h0out[(size_t)r * NFC + g] = v;
        }
    }
}

// ---------------------------------------------------------------------------
extern "C" void kernel_launch(void* const* d_in, const int* in_sizes, int n_in,
                              void* d_out, int out_size)
{
    const float* z     = (const float*)d_in[0];
    const float* c     = (const float*)d_in[1];
    const float* fc1_w = (const float*)d_in[2];
    const float* fc1_b = (const float*)d_in[3];
    const float* w_ih  = (const float*)d_in[4];
    const float* w_hh  = (const float*)d_in[5];
    const float* b_ih  = (const float*)d_in[6];
    const float* b_hh  = (const float*)d_in[7];
    float* out = (float*)d_out;

    uint32_t *xA, *xB;
    float *h0Buf;
    cudaGetSymbolAddress((void**)&xA,    g_x16A);
    cudaGetSymbolAddress((void**)&xB,    g_x16B);
    cudaGetSymbolAddress((void**)&h0Buf, g_h0);

    constexpr int NFR = 12 * 18 * 32;
    const size_t smF = (size_t)NFR * 8 + (size_t)NFR * 8
                     + (size_t)(4 * 32 * HP2) * sizeof(__half)
                     + (size_t)(2 * G_) * sizeof(float);        // 139,520 B
    const size_t sm0 = (size_t)(2 * 32 * HP2) * sizeof(__half)
                     + (size_t)(2 * G_) * sizeof(float);        // 15,616 B
    const size_t fcSm = (size_t)(KC * NFCP + KC * HPf) * sizeof(float);

    cudaFuncSetAttribute((const void*)scanF<false, false>, cudaFuncAttributeMaxDynamicSharedMemorySize, (int)sm0);
    cudaFuncSetAttribute((const void*)scanF<true,  false>, cudaFuncAttributeMaxDynamicSharedMemorySize, (int)smF);
    cudaFuncSetAttribute((const void*)scanF<true,  true>,  cudaFuncAttributeMaxDynamicSharedMemorySize, (int)smF);
    cudaFuncSetAttribute((const void*)fc1_kernel,           cudaFuncAttributeMaxDynamicSharedMemorySize, (int)fcSm);

    const int nblk = B_ / NB_;  // 128

    fc1_kernel<<<nblk, 256, fcSm>>>(z, c, fc1_w, fc1_b, h0Buf);

    // layer 0: input zeros -> fp16 activations into xA
    scanF<false, false><<<nblk, THR, sm0>>>(w_hh, b_hh, nullptr, b_ih,
                                            h0Buf, nullptr, xA, nullptr);

    // layer 1: xA -> xB
    scanF<true, false><<<nblk, THR, smF>>>(w_hh + 1 * (size_t)G_ * H_, b_hh + 1 * G_,
                                           w_ih + 1 * (size_t)G_ * H_, b_ih + 1 * G_,
                                           h0Buf + 1 * (size_t)B_ * H_, xA, xB, nullptr);
    // layer 2: xB -> xA
    scanF<true, false><<<nblk, THR, smF>>>(w_hh + 2 * (size_t)G_ * H_, b_hh + 2 * G_,
                                           w_ih + 2 * (size_t)G_ * H_, b_ih + 2 * G_,
                                           h0Buf + 2 * (size_t)B_ * H_, xB, xA, nullptr);
    // layer 3: xA -> out [B,H,T] directly (transpose folded in)
    scanF<true, true><<<nblk, THR, smF>>>(w_hh + 3 * (size_t)G_ * H_, b_hh + 3 * G_,
                                          w_ih + 3 * (size_t)G_ * H_, b_ih + 3 * G_,
                                          h0Buf + 3 * (size_t)B_ * H_, xA, nullptr, out);
}

// round 14
// speedup vs baseline: 1.3119x; 1.1439x over previous
#include <cuda_runtime.h>
#include <cuda_fp16.h>
#include <cstdint>
#include <cstddef>

// ---------------------------------------------------------------------------
constexpr int H_  = 96;
constexpr int G_  = 288;
constexpr int T_  = 239;
constexpr int B_  = 4096;
constexpr int NB_ = 32;
constexpr int HW  = 48;    // H/2 packed words per row

constexpr int HP2 = 104;   // fp16 pitch for A (h/x) ldmatrix tiles
constexpr int THR = 768;   // 24 warps: 12 j-groups x 2 m-groups

constexpr int KIN  = 512;
constexpr int NFC  = 384;
constexpr int NFCP = 385;
constexpr int KC   = 64;
constexpr int HPf  = 33;

constexpr size_t SZ_X16 = (size_t)T_ * B_ * HW;   // packed fp16 activations
constexpr size_t SZ_H0  = (size_t)B_ * NFC;

__device__ uint32_t g_x16A[SZ_X16];
__device__ uint32_t g_x16B[SZ_X16];
__device__ float    g_h0  [SZ_H0];

// ---------------------------------------------------------------------------
__device__ __forceinline__ float ex2f(float x) {
    float y; asm("ex2.approx.f32 %0, %1;" : "=f"(y) : "f"(x)); return y;
}
__device__ __forceinline__ float rcpf(float x) {
    float y; asm("rcp.approx.f32 %0, %1;" : "=f"(y) : "f"(x)); return y;
}
constexpr float L2E = 1.4426950408889634f;

__device__ __forceinline__ uint32_t pack_h2(__half a, __half b) {
    return (uint32_t)__half_as_ushort(a) | ((uint32_t)__half_as_ushort(b) << 16);
}
__device__ __forceinline__ void split2h(float x, __half& h, __half& l) {
    h = __float2half_rn(x);
    l = __float2half_rn(x - __half2float(h));
}

__device__ __forceinline__ void mma16816(float c[4], const uint32_t a[4], const uint32_t b0, const uint32_t b1) {
    asm volatile(
        "mma.sync.aligned.m16n8k16.row.col.f32.f16.f16.f32 "
        "{%0,%1,%2,%3}, {%4,%5,%6,%7}, {%8,%9}, {%0,%1,%2,%3};"
        : "+f"(c[0]), "+f"(c[1]), "+f"(c[2]), "+f"(c[3])
        : "r"(a[0]), "r"(a[1]), "r"(a[2]), "r"(a[3]), "r"(b0), "r"(b1));
}
__device__ __forceinline__ void ldsm4(uint32_t r[4], uint32_t addr) {
    asm volatile("ldmatrix.sync.aligned.m8n8.x4.shared.b16 {%0,%1,%2,%3}, [%4];"
                 : "=r"(r[0]), "=r"(r[1]), "=r"(r[2]), "=r"(r[3]) : "r"(addr));
}
__device__ __forceinline__ void cpasync16(uint32_t smem_addr, const void* gptr) {
    asm volatile("cp.async.cg.shared.global [%0], [%1], 16;" :: "r"(smem_addr), "l"(gptr));
}
__device__ __forceinline__ void cpasync_commit() {
    asm volatile("cp.async.commit_group;" ::: "memory");
}
__device__ __forceinline__ void cpasync_wait0() {
    asm volatile("cp.async.wait_group 0;" ::: "memory");
}
__device__ __forceinline__ void cpasync_wait1() {
    asm volatile("cp.async.wait_group 1;" ::: "memory");
}
// Named barrier over one m-group (384 threads). Groups 1 and 2.
__device__ __forceinline__ void barg(int id) {
    asm volatile("bar.sync %0, 384;" :: "r"(id) : "memory");
}

// ---------------------------------------------------------------------------
// Fused GRU scan, 24 warps (m-split), per-m-group named barriers (the two
// groups are state-disjoint: each owns 16 rows of hb/xb; only j-exchange
// within a group couples warps). h-GEMM: 2-term fp16 weights (hi regs, lo
// smem when FUSED / regs when not). x-GEMM: single-term fp16 (smem).
// n-gate input term accumulated separately (cx) — stays outside r*(...).
// ---------------------------------------------------------------------------
template <bool FUSED, bool LAST>
__global__ void __launch_bounds__(THR, 1)
scanF(const float* __restrict__ w_hh, const float* __restrict__ b_hh,
      const float* __restrict__ w_ih, const float* __restrict__ b_ih,
      const float* __restrict__ h0,   const uint32_t* __restrict__ xg,
      uint32_t* __restrict__ outg,    float* __restrict__ outf)
{
    extern __shared__ __align__(16) char smraw[];
    constexpr int NFR = 12 * 18 * 32;
    uint2*  wpIh = (uint2*)smraw;
    uint2*  wpLo = (uint2*)(smraw + (FUSED ? NFR * 8 : 0));
    __half* hb   = (__half*)((char*)wpLo + (FUSED ? NFR * 8 : 0));
    __half* xb   = hb + 2 * 32 * HP2;
    float* bias_s = (float*)(xb + (FUSED ? 2 * 32 * HP2 : 0));

    const int tid  = threadIdx.x;
    const int lane = tid & 31;
    const int w    = tid >> 5;          // 0..23
    const int wj   = w % 12;            // j-group
    const int mg   = w / 12;            // m-group (0: rows 0-15, 1: rows 16-31)
    const int b0   = blockIdx.x * NB_;

    // --- w_hh: hi fragments -> regs; lo -> smem (FUSED) or regs (!FUSED) ---
    uint32_t bhi[6][3][2];
    uint32_t bloR[6][3][2];   // used only when !FUSED
#pragma unroll
    for (int kt = 0; kt < 6; ++kt)
#pragma unroll
        for (int nt = 0; nt < 3; ++nt) {
            const int g  = nt * 96 + 8 * wj + (lane >> 2);
            const int k0 = kt * 16 + (lane & 3) * 2;
            const float* p = w_hh + (size_t)g * H_ + k0;
            float w0 = p[0], w1 = p[1], w2 = p[8], w3 = p[9];
            __half h0b, h1b, h2b, h3b, l0b, l1b, l2b, l3b;
            split2h(w0, h0b, l0b); split2h(w1, h1b, l1b);
            split2h(w2, h2b, l2b); split2h(w3, h3b, l3b);
            bhi[kt][nt][0] = pack_h2(h0b, h1b);
            bhi[kt][nt][1] = pack_h2(h2b, h3b);
            if constexpr (FUSED) {
                if (mg == 0) {
                    uint2 lv;
                    lv.x = pack_h2(l0b, l1b);
                    lv.y = pack_h2(l2b, l3b);
                    wpLo[(wj * 18 + kt * 3 + nt) * 32 + lane] = lv;
                }
            } else {
                bloR[kt][nt][0] = pack_h2(l0b, l1b);
                bloR[kt][nt][1] = pack_h2(l2b, l3b);
            }
        }

    // --- w_ih hi-only fragments in smem (FUSED; mg 0 writes) ---
    if constexpr (FUSED) {
        if (mg == 0) {
#pragma unroll
            for (int kt = 0; kt < 6; ++kt)
#pragma unroll
                for (int nt = 0; nt < 3; ++nt) {
                    const int g  = nt * 96 + 8 * wj + (lane >> 2);
                    const int k0 = kt * 16 + (lane & 3) * 2;
                    const float* p = w_ih + (size_t)g * H_ + k0;
                    uint2 v;
                    v.x = pack_h2(__float2half_rn(p[0]), __float2half_rn(p[1]));
                    v.y = pack_h2(__float2half_rn(p[8]), __float2half_rn(p[9]));
                    wpIh[(wj * 18 + kt * 3 + nt) * 32 + lane] = v;
                }
        }
    }
    if (tid < G_) {
        bias_s[tid]      = b_hh[tid];
        bias_s[G_ + tid] = b_ih[tid];
    }

    const int crow = lane >> 2;
    const int jc   = 8 * wj + 2 * (lane & 3);
    const int rbase = mg * 16 + crow;     // + rh*8

    // --- init h state (this warp's 16 rows only) ---
    float hold[4];   // [rh*2+col]
#pragma unroll
    for (int rh = 0; rh < 2; ++rh) {
        const int row = rbase + rh * 8;
        const float2 v = *(const float2*)&h0[(size_t)(b0 + row) * H_ + jc];
        hold[rh * 2]     = v.x;
        hold[rh * 2 + 1] = v.y;
        *(uint32_t*)&hb[0 * 32 * HP2 + row * HP2 + jc] =
            pack_h2(__float2half_rn(v.x), __float2half_rn(v.y));
    }

    // --- cp.async mapping, per m-group: 192 active threads load the group's
    //     16 rows (16 rows x 12 chunks of 16B). Group-private xb halves.
    const int gidx    = tid - mg * 384;          // 0..383 within group
    const bool cpon   = (gidx < 192);
    const int cprow   = mg * 16 + gidx / 12;
    const int cpchunk = gidx - (gidx / 12) * 12;
    const uint32_t xbS = (uint32_t)__cvta_generic_to_shared(xb)
                       + (uint32_t)(cprow * HP2 * 2 + cpchunk * 16);
    const uint32_t* xsrc0 = nullptr;
    constexpr uint32_t BUFB = (uint32_t)(32 * HP2 * 2);
    if constexpr (FUSED) {
        if (cpon) {
            xsrc0 = xg + (size_t)(b0 + cprow) * HW + cpchunk * 4;
            cpasync16(xbS, xsrc0);                          // x(0) -> xb[0]
            cpasync_commit();
            cpasync16(xbS + BUFB, xsrc0 + (size_t)B_ * HW); // x(1) -> xb[1]
            cpasync_commit();
            cpasync_wait1();                                // x(0) done
        }
    }
    __syncthreads();   // one full sync: weights/bias/init state visible

    // ldmatrix per-lane offsets (16-row tile of this m-group)
    const int arow = (lane & 7) + ((lane >> 3) & 1) * 8;
    const int acol = ((lane >> 4) & 1) * 8;
    const uint32_t lofs = (uint32_t)(((mg * 16 + arow) * HP2 + acol) * 2);
    const uint32_t hBase = (uint32_t)__cvta_generic_to_shared(hb) + lofs;
    const uint32_t xBase = (uint32_t)__cvta_generic_to_shared(xb) + lofs;

    const uint2* wpIhB = wpIh + (wj * 18) * 32 + lane;
    const uint2* wpLoB = wpLo + (wj * 18) * 32 + lane;

    float c[3][4];   // r, z, n(hidden)
    float cx[4];     // n(input) — separate (stays outside r*(...))

    // prologue: x-GEMM for t=0 (hi-only weights)
    if constexpr (FUSED) {
#pragma unroll
        for (int nt = 0; nt < 3; ++nt)
#pragma unroll
            for (int q = 0; q < 4; ++q) c[nt][q] = 0.f;
#pragma unroll
        for (int q = 0; q < 4; ++q) cx[q] = 0.f;
#pragma unroll
        for (int kt = 0; kt < 6; ++kt) {
            uint32_t xh[4];
            ldsm4(xh, xBase + (uint32_t)(kt * 32));
            uint2 v0 = wpIhB[(kt * 3 + 0) * 32];
            uint2 v1 = wpIhB[(kt * 3 + 1) * 32];
            uint2 v2 = wpIhB[(kt * 3 + 2) * 32];
            mma16816(c[0], xh, v0.x, v0.y);
            mma16816(c[1], xh, v1.x, v1.y);
            mma16816(cx,   xh, v2.x, v2.y);
        }
    }

    const int barId = 1 + mg;

    for (int t = 0; t < T_; ++t) {
        const int p  = t & 1;
        const int pn = p ^ 1;

        if constexpr (FUSED) {
            if (cpon) cpasync_wait0();   // this group's x(t+1) complete
        } else {
#pragma unroll
            for (int nt = 0; nt < 3; ++nt)
#pragma unroll
                for (int q = 0; q < 4; ++q) c[nt][q] = 0.f;
#pragma unroll
            for (int q = 0; q < 4; ++q) cx[q] = 0.f;
        }
        barg(barId);    // group-local: h(t)/x(t+1) rows of THIS group visible

        // stream x(t+2) into this group's xb[p] rows
        if constexpr (FUSED) {
            if (cpon) {
                const int tn2 = (t + 2 < T_) ? (t + 2) : (T_ - 1);
                cpasync16(xbS + (uint32_t)p * BUFB, xsrc0 + (size_t)tn2 * B_ * HW);
                cpasync_commit();
            }
        }

        // h-GEMM for step t (hi regs; lo from smem when FUSED, regs otherwise)
        const uint32_t aH = hBase + (uint32_t)p * BUFB;
#pragma unroll
        for (int kt = 0; kt < 6; ++kt) {
            uint32_t ah[4];
            ldsm4(ah, aH + (uint32_t)(kt * 32));
            mma16816(c[0], ah, bhi[kt][0][0], bhi[kt][0][1]);
            mma16816(c[1], ah, bhi[kt][1][0], bhi[kt][1][1]);
            mma16816(c[2], ah, bhi[kt][2][0], bhi[kt][2][1]);
            if constexpr (FUSED) {
                uint2 l0 = wpLoB[(kt * 3 + 0) * 32];
                uint2 l1 = wpLoB[(kt * 3 + 1) * 32];
                uint2 l2 = wpLoB[(kt * 3 + 2) * 32];
                mma16816(c[0], ah, l0.x, l0.y);
                mma16816(c[1], ah, l1.x, l1.y);
                mma16816(c[2], ah, l2.x, l2.y);
            } else {
                mma16816(c[0], ah, bloR[kt][0][0], bloR[kt][0][1]);
                mma16816(c[1], ah, bloR[kt][1][0], bloR[kt][1][1]);
                mma16816(c[2], ah, bloR[kt][2][0], bloR[kt][2][1]);
            }
        }

        // elementwise + stores (4 elements per thread); shared-rcp sigmoids
        const float2 bh0 = *(const float2*)&bias_s[0 * 96 + jc];
        const float2 bh1 = *(const float2*)&bias_s[1 * 96 + jc];
        const float2 bh2 = *(const float2*)&bias_s[2 * 96 + jc];
        const float2 bi0 = *(const float2*)&bias_s[G_ + 0 * 96 + jc];
        const float2 bi1 = *(const float2*)&bias_s[G_ + 1 * 96 + jc];
        const float2 bi2 = *(const float2*)&bias_s[G_ + 2 * 96 + jc];
#pragma unroll
        for (int rh = 0; rh < 2; ++rh) {
            const int row = rbase + rh * 8;
            float hn2[2];
#pragma unroll
            for (int col = 0; col < 2; ++col) {
                const int q = rh * 2 + col;
                const float bhr = (col == 0) ? bh0.x : bh0.y;
                const float bhz = (col == 0) ? bh1.x : bh1.y;
                const float bhn = (col == 0) ? bh2.x : bh2.y;
                const float bir = (col == 0) ? bi0.x : bi0.y;
                const float biz = (col == 0) ? bi1.x : bi1.y;
                const float bin = (col == 0) ? bi2.x : bi2.y;
                const float ar = bir + c[0][q] + bhr;
                const float az = biz + c[1][q] + bhz;
                const float u  = 1.f + ex2f(-L2E * ar);
                const float v  = 1.f + ex2f(-L2E * az);
                const float wv = rcpf(u * v);
                const float rg = v * wv;              // sigmoid(ar)
                const float zg = u * wv;              // sigmoid(az)
                const float na = bin + cx[q] + rg * (c[2][q] + bhn);
                const float s  = 1.f + ex2f(-2.f * L2E * na);
                const float ng = 2.f * rcpf(s) - 1.f; // tanh(na)
                const float hv = ng + zg * (hold[q] - ng);
                hold[q] = hv;
                hn2[col] = hv;
            }
            const uint32_t ph = pack_h2(__float2half_rn(hn2[0]), __float2half_rn(hn2[1]));
            *(uint32_t*)&hb[pn * 32 * HP2 + row * HP2 + jc] = ph;
            if constexpr (LAST) {
                const int ob = ((b0 + row) * H_ + jc) * T_ + t;
                outf[ob]      = hn2[0];
                outf[ob + T_] = hn2[1];
            } else {
                outg[(size_t)(t * B_ + b0 + row) * HW + (jc >> 1)] = ph;
            }
        }

        // x-GEMM for step t+1 (hi-only; fills the pre-barrier gap)
        if constexpr (FUSED) {
            if (t + 1 < T_) {
                const uint32_t aX = xBase + (uint32_t)pn * BUFB;
#pragma unroll
                for (int nt = 0; nt < 3; ++nt)
#pragma unroll
                    for (int q = 0; q < 4; ++q) c[nt][q] = 0.f;
#pragma unroll
                for (int q = 0; q < 4; ++q) cx[q] = 0.f;
#pragma unroll
                for (int kt = 0; kt < 6; ++kt) {
                    uint32_t xh[4];
                    ldsm4(xh, aX + (uint32_t)(kt * 32));
                    uint2 v0 = wpIhB[(kt * 3 + 0) * 32];
                    uint2 v1 = wpIhB[(kt * 3 + 1) * 32];
                    uint2 v2 = wpIhB[(kt * 3 + 2) * 32];
                    mma16816(c[0], xh, v0.x, v0.y);
                    mma16816(c[1], xh, v1.x, v1.y);
                    mma16816(cx,   xh, v2.x, v2.y);
                }
            }
        }
    }
}

// ---------------------------------------------------------------------------
// fc1 (fp32, tiny)
// ---------------------------------------------------------------------------
__global__ void __launch_bounds__(256, 1)
fc1_kernel(const float* __restrict__ z, const float* __restrict__ c,
           const float* __restrict__ w, const float* __restrict__ bias,
           float* __restrict__ h0out)
{
    extern __shared__ float sm[];
    float* wc_s = sm;
    float* xc_s = wc_s + KC * NFCP;

    const int tid = threadIdx.x;
    const int cx  = tid & 31;
    const int ry  = tid >> 5;
    const int b0  = blockIdx.x * NB_;

    float acc[4][12];
#pragma unroll
    for (int m = 0; m < 4; ++m)
#pragma unroll
        for (int i = 0; i < 12; ++i) acc[m][i] = 0.f;

    for (int kc = 0; kc < KIN; kc += KC) {
        for (int idx = tid; idx < NFC * KC; idx += 256) {
            int g = idx / KC, kk = idx - g * KC;
            wc_s[kk * NFCP + g] = w[(size_t)g * KIN + kc + kk];
        }
        for (int idx = tid; idx < NB_ * KC; idx += 256) {
            int r = idx / KC, kk = idx - r * KC;
            int k = kc + kk;
            float v = (k < 256) ? z[(size_t)(b0 + r) * 256 + k]
                                : c[(size_t)(b0 + r) * 256 + (k - 256)];
            xc_s[kk * HPf + r] = v;
        }
        __syncthreads();
#pragma unroll 4
        for (int kk = 0; kk < KC; ++kk) {
            const float a0 = xc_s[kk * HPf + ry +  0];
            const float a1 = xc_s[kk * HPf + ry +  8];
            const float a2 = xc_s[kk * HPf + ry + 16];
            const float a3 = xc_s[kk * HPf + ry + 24];
            const float* wr = wc_s + kk * NFCP + cx;
#pragma unroll
            for (int i = 0; i < 12; ++i) {
                const float wv = wr[32 * i];
                acc[0][i] = fmaf(a0, wv, acc[0][i]);
                acc[1][i] = fmaf(a1, wv, acc[1][i]);
                acc[2][i] = fmaf(a2, wv, acc[2][i]);
                acc[3][i] = fmaf(a3, wv, acc[3][i]);
            }
        }
        __syncthreads();
    }

#pragma unroll
    for (int m = 0; m < 4; ++m) {
        const int r = b0 + ry + 8 * m;
#pragma unroll
        for (int i = 0; i < 12; ++i) {
            const int g = cx + 32 * i;
            float v = acc[m][i] + bias[g];
            v = (v >= 0.f) ? v : 0.2f * v;
            h0out[(size_t)r * NFC + g] = v;
        }
    }
}

// ---------------------------------------------------------------------------
extern "C" void kernel_launch(void* const* d_in, const int* in_sizes, int n_in,
                              void* d_out, int out_size)
{
    const float* z     = (const float*)d_in[0];
    const float* c     = (const float*)d_in[1];
    const float* fc1_w = (const float*)d_in[2];
    const float* fc1_b = (const float*)d_in[3];
    const float* w_ih  = (const float*)d_in[4];
    const float* w_hh  = (const float*)d_in[5];
    const float* b_ih  = (const float*)d_in[6];
    const float* b_hh  = (const float*)d_in[7];
    float* out = (float*)d_out;

    uint32_t *xA, *xB;
    float *h0Buf;
    cudaGetSymbolAddress((void**)&xA,    g_x16A);
    cudaGetSymbolAddress((void**)&xB,    g_x16B);
    cudaGetSymbolAddress((void**)&h0Buf, g_h0);

    constexpr int NFR = 12 * 18 * 32;
    const size_t smF = (size_t)NFR * 8 + (size_t)NFR * 8
                     + (size_t)(4 * 32 * HP2) * sizeof(__half)
                     + (size_t)(2 * G_) * sizeof(float);        // 139,520 B
    const size_t sm0 = (size_t)(2 * 32 * HP2) * sizeof(__half)
                     + (size_t)(2 * G_) * sizeof(float);        // 15,616 B
    const size_t fcSm = (size_t)(KC * NFCP + KC * HPf) * sizeof(float);

    cudaFuncSetAttribute((const void*)scanF<false, false>, cudaFuncAttributeMaxDynamicSharedMemorySize, (int)sm0);
    cudaFuncSetAttribute((const void*)scanF<true,  false>, cudaFuncAttributeMaxDynamicSharedMemorySize, (int)smF);
    cudaFuncSetAttribute((const void*)scanF<true,  true>,  cudaFuncAttributeMaxDynamicSharedMemorySize, (int)smF);
    cudaFuncSetAttribute((const void*)fc1_kernel,           cudaFuncAttributeMaxDynamicSharedMemorySize, (int)fcSm);

    const int nblk = B_ / NB_;  // 128

    fc1_kernel<<<nblk, 256, fcSm>>>(z, c, fc1_w, fc1_b, h0Buf);

    // layer 0: input zeros -> fp16 activations into xA
    scanF<false, false><<<nblk, THR, sm0>>>(w_hh, b_hh, nullptr, b_ih,
                                            h0Buf, nullptr, xA, nullptr);

    // layer 1: xA -> xB
    scanF<true, false><<<nblk, THR, smF>>>(w_hh + 1 * (size_t)G_ * H_, b_hh + 1 * G_,
                                           w_ih + 1 * (size_t)G_ * H_, b_ih + 1 * G_,
                                           h0Buf + 1 * (size_t)B_ * H_, xA, xB, nullptr);
    // layer 2: xB -> xA
    scanF<true, false><<<nblk, THR, smF>>>(w_hh + 2 * (size_t)G_ * H_, b_hh + 2 * G_,
                                           w_ih + 2 * (size_t)G_ * H_, b_ih + 2 * G_,
                                           h0Buf + 2 * (size_t)B_ * H_, xB, xA, nullptr);
    // layer 3: xA -> out [B,H,T] directly (transpose folded in)
    scanF<true, true><<<nblk, THR, smF>>>(w_hh + 3 * (size_t)G_ * H_, b_hh + 3 * G_,
                                          w_ih + 3 * (size_t)G_ * H_, b_ih + 3 * G_,
                                          h0Buf + 3 * (size_t)B_ * H_, xA, nullptr, out);
}

// round 15
// speedup vs baseline: 1.3401x; 1.0215x over previous
#include <cuda_runtime.h>
#include <cuda_fp16.h>
#include <cstdint>
#include <cstddef>

// ---------------------------------------------------------------------------
constexpr int H_  = 96;
constexpr int G_  = 288;
constexpr int T_  = 239;
constexpr int B_  = 4096;
constexpr int NB_ = 32;
constexpr int HW  = 48;    // H/2 packed words per row

constexpr int HP2 = 104;   // fp16 pitch for A (h/x) ldmatrix tiles
constexpr int THR = 768;   // 24 warps: 12 j-groups x 2 m-groups

constexpr int KIN  = 512;
constexpr int NFC  = 384;
constexpr int NFCP = 385;
constexpr int KC   = 64;
constexpr int HPf  = 33;

constexpr size_t SZ_X16 = (size_t)T_ * B_ * HW;
constexpr size_t SZ_H0  = (size_t)B_ * NFC;

__device__ uint32_t g_x16A[SZ_X16];
__device__ uint32_t g_x16B[SZ_X16];
__device__ float    g_h0  [SZ_H0];

// ---------------------------------------------------------------------------
__device__ __forceinline__ float ex2f(float x) {
    float y; asm("ex2.approx.f32 %0, %1;" : "=f"(y) : "f"(x)); return y;
}
__device__ __forceinline__ float rcpf(float x) {
    float y; asm("rcp.approx.f32 %0, %1;" : "=f"(y) : "f"(x)); return y;
}
constexpr float L2E = 1.4426950408889634f;

__device__ __forceinline__ uint32_t pack_h2(__half a, __half b) {
    return (uint32_t)__half_as_ushort(a) | ((uint32_t)__half_as_ushort(b) << 16);
}
__device__ __forceinline__ void split2h(float x, __half& h, __half& l) {
    h = __float2half_rn(x);
    l = __float2half_rn(x - __half2float(h));
}

__device__ __forceinline__ void mma16816(float c[4], const uint32_t a[4],
                                         const uint32_t b0, const uint32_t b1) {
    asm volatile(
        "mma.sync.aligned.m16n8k16.row.col.f32.f16.f16.f32 "
        "{%0,%1,%2,%3}, {%4,%5,%6,%7}, {%8,%9}, {%0,%1,%2,%3};"
        : "+f"(c[0]), "+f"(c[1]), "+f"(c[2]), "+f"(c[3])
        : "r"(a[0]), "r"(a[1]), "r"(a[2]), "r"(a[3]), "r"(b0), "r"(b1));
}
__device__ __forceinline__ void ldsm4(uint32_t r[4], uint32_t addr) {
    asm volatile("ldmatrix.sync.aligned.m8n8.x4.shared.b16 {%0,%1,%2,%3}, [%4];"
                 : "=r"(r[0]), "=r"(r[1]), "=r"(r[2]), "=r"(r[3]) : "r"(addr));
}
__device__ __forceinline__ void lds2(uint32_t addr, uint32_t& x, uint32_t& y) {
    asm volatile("ld.shared.v2.u32 {%0,%1}, [%2];" : "=r"(x), "=r"(y) : "r"(addr));
}
__device__ __forceinline__ float2 lds2f(uint32_t addr) {
    float2 v;
    asm volatile("ld.shared.v2.f32 {%0,%1}, [%2];" : "=f"(v.x), "=f"(v.y) : "r"(addr));
    return v;
}
__device__ __forceinline__ void cpasync16(uint32_t smem_addr, const void* gptr) {
    asm volatile("cp.async.cg.shared.global [%0], [%1], 16;" :: "r"(smem_addr), "l"(gptr));
}
__device__ __forceinline__ void cpasync_commit() {
    asm volatile("cp.async.commit_group;" ::: "memory");
}
__device__ __forceinline__ void cpasync_wait0() {
    asm volatile("cp.async.wait_group 0;" ::: "memory");
}
__device__ __forceinline__ void barg(int id) {
    asm volatile("bar.sync %0, 384;" :: "r"(id) : "memory");
}

// ---------------------------------------------------------------------------
// h-GEMM: accumulate gh(t) onto c. hi weights from regs; lo from smem (FUSED)
// or regs (!FUSED).
// ---------------------------------------------------------------------------
template <bool FUSED>
__device__ __forceinline__ void hgemm(uint32_t aH,
                                      const uint32_t (&bhi)[6][3][2],
                                      const uint32_t (&bloR)[6][3][2],
                                      uint32_t wpLoS, float (&c)[3][4]) {
#pragma unroll
    for (int kt = 0; kt < 6; ++kt) {
        uint32_t ah[4];
        ldsm4(ah, aH + (uint32_t)(kt * 32));
        mma16816(c[0], ah, bhi[kt][0][0], bhi[kt][0][1]);
        mma16816(c[1], ah, bhi[kt][1][0], bhi[kt][1][1]);
        mma16816(c[2], ah, bhi[kt][2][0], bhi[kt][2][1]);
        if constexpr (FUSED) {
            uint32_t l0x, l0y, l1x, l1y, l2x, l2y;
            lds2(wpLoS + (uint32_t)((kt * 3 + 0) * 256), l0x, l0y);
            lds2(wpLoS + (uint32_t)((kt * 3 + 1) * 256), l1x, l1y);
            lds2(wpLoS + (uint32_t)((kt * 3 + 2) * 256), l2x, l2y);
            mma16816(c[0], ah, l0x, l0y);
            mma16816(c[1], ah, l1x, l1y);
            mma16816(c[2], ah, l2x, l2y);
        } else {
            mma16816(c[0], ah, bloR[kt][0][0], bloR[kt][0][1]);
            mma16816(c[1], ah, bloR[kt][1][0], bloR[kt][1][1]);
            mma16816(c[2], ah, bloR[kt][2][0], bloR[kt][2][1]);
        }
    }
}

// ---------------------------------------------------------------------------
// Double x-GEMM: compute gi(even t) -> c/cx and gi(odd t) -> g2/g2x, sharing
// each w_ih fragment load across both A tiles. Accumulators initialized with
// folded biases (r,z: b_ih+b_hh; n input part: b_ih).
// ---------------------------------------------------------------------------
__device__ __forceinline__ void xgemm2(uint32_t aX0, uint32_t aX1, uint32_t wpIhS,
                                       float2 cr, float2 cz, float2 bn,
                                       float (&c)[3][4], float (&cx)[4],
                                       float (&g2)[3][4], float (&g2x)[4]) {
#pragma unroll
    for (int q = 0; q < 4; ++q) {
        const bool od = q & 1;
        const float r0 = od ? cr.y : cr.x;
        const float z0 = od ? cz.y : cz.x;
        const float n0 = od ? bn.y : bn.x;
        c[0][q] = r0;  c[1][q] = z0;  c[2][q] = 0.f;  cx[q] = n0;
        g2[0][q] = r0; g2[1][q] = z0; g2[2][q] = 0.f; g2x[q] = n0;
    }
#pragma unroll
    for (int kt = 0; kt < 6; ++kt) {
        uint32_t x0[4], x1[4];
        ldsm4(x0, aX0 + (uint32_t)(kt * 32));
        ldsm4(x1, aX1 + (uint32_t)(kt * 32));
        uint32_t v0x, v0y, v1x, v1y, v2x, v2y;
        lds2(wpIhS + (uint32_t)((kt * 3 + 0) * 256), v0x, v0y);
        lds2(wpIhS + (uint32_t)((kt * 3 + 1) * 256), v1x, v1y);
        lds2(wpIhS + (uint32_t)((kt * 3 + 2) * 256), v2x, v2y);
        mma16816(c[0],  x0, v0x, v0y);
        mma16816(c[1],  x0, v1x, v1y);
        mma16816(cx,    x0, v2x, v2y);
        mma16816(g2[0], x1, v0x, v0y);
        mma16816(g2[1], x1, v1x, v1y);
        mma16816(g2x,   x1, v2x, v2y);
    }
}

// ---------------------------------------------------------------------------
// Elementwise + state/output stores for one step (biases pre-folded; bhn
// separate). Writes h into hbw (next-phase buffer).
// ---------------------------------------------------------------------------
template <bool LAST>
__device__ __forceinline__ void elem_store(const float (&c)[3][4], const float (&cx)[4],
                                           float (&hold)[4], float2 bhn2,
                                           int rbase, int jc, int b0, int t,
                                           __half* hbw,
                                           uint32_t* __restrict__ outg,
                                           float* __restrict__ outf) {
#pragma unroll
    for (int rh = 0; rh < 2; ++rh) {
        const int row = rbase + rh * 8;
        float hn2[2];
#pragma unroll
        for (int col = 0; col < 2; ++col) {
            const int q = rh * 2 + col;
            const float bhn = col ? bhn2.y : bhn2.x;
            const float ar = c[0][q];
            const float az = c[1][q];
            const float u  = 1.f + ex2f(-L2E * ar);
            const float v  = 1.f + ex2f(-L2E * az);
            const float wv = rcpf(u * v);
            const float rg = v * wv;              // sigmoid(ar)
            const float zg = u * wv;              // sigmoid(az)
            const float na = cx[q] + rg * (c[2][q] + bhn);
            const float s  = 1.f + ex2f(-2.f * L2E * na);
            const float ng = 2.f * rcpf(s) - 1.f; // tanh(na)
            const float hv = ng + zg * (hold[q] - ng);
            hold[q] = hv;
            hn2[col] = hv;
        }
        const uint32_t ph = pack_h2(__float2half_rn(hn2[0]), __float2half_rn(hn2[1]));
        *(uint32_t*)&hbw[row * HP2 + jc] = ph;
        if constexpr (LAST) {
            const int ob = ((b0 + row) * H_ + jc) * T_ + t;
            outf[ob]      = hn2[0];
            outf[ob + T_] = hn2[1];
        } else {
            outg[(size_t)(t * B_ + b0 + row) * HW + (jc >> 1)] = ph;
        }
    }
}

// ---------------------------------------------------------------------------
// Fused GRU scan, 24 warps (m-split), per-group named barriers, t-loop
// unrolled by 2 with shared x-weight fragment loads (FUSED).
// ---------------------------------------------------------------------------
template <bool FUSED, bool LAST>
__global__ void __launch_bounds__(THR, 1)
scanF(const float* __restrict__ w_hh, const float* __restrict__ b_hh,
      const float* __restrict__ w_ih, const float* __restrict__ b_ih,
      const float* __restrict__ h0,   const uint32_t* __restrict__ xg,
      uint32_t* __restrict__ outg,    float* __restrict__ outf)
{
    extern __shared__ __align__(16) char smraw[];
    constexpr int NFR = 12 * 18 * 32;
    uint2*  wpIh = (uint2*)smraw;
    uint2*  wpLo = (uint2*)(smraw + (FUSED ? NFR * 8 : 0));
    __half* hb   = (__half*)((char*)wpLo + (FUSED ? NFR * 8 : 0));
    __half* xb   = hb + 2 * 32 * HP2;
    float* bias_s = (float*)(xb + (FUSED ? 2 * 32 * HP2 : 0));   // 384 floats (FUSED)

    const int tid  = threadIdx.x;
    const int lane = tid & 31;
    const int w    = tid >> 5;          // 0..23
    const int wj   = w % 12;
    const int mg   = w / 12;
    const int b0   = blockIdx.x * NB_;

    // --- w_hh: hi -> regs; lo -> smem (FUSED) or regs (!FUSED) ---
    uint32_t bhi[6][3][2];
    uint32_t bloR[6][3][2];
#pragma unroll
    for (int kt = 0; kt < 6; ++kt)
#pragma unroll
        for (int nt = 0; nt < 3; ++nt) {
            const int g  = nt * 96 + 8 * wj + (lane >> 2);
            const int k0 = kt * 16 + (lane & 3) * 2;
            const float* p = w_hh + (size_t)g * H_ + k0;
            float w0 = p[0], w1 = p[1], w2 = p[8], w3 = p[9];
            __half h0b, h1b, h2b, h3b, l0b, l1b, l2b, l3b;
            split2h(w0, h0b, l0b); split2h(w1, h1b, l1b);
            split2h(w2, h2b, l2b); split2h(w3, h3b, l3b);
            bhi[kt][nt][0] = pack_h2(h0b, h1b);
            bhi[kt][nt][1] = pack_h2(h2b, h3b);
            if constexpr (FUSED) {
                if (mg == 0) {
                    uint2 lv;
                    lv.x = pack_h2(l0b, l1b);
                    lv.y = pack_h2(l2b, l3b);
                    wpLo[(wj * 18 + kt * 3 + nt) * 32 + lane] = lv;
                }
            } else {
                bloR[kt][nt][0] = pack_h2(l0b, l1b);
                bloR[kt][nt][1] = pack_h2(l2b, l3b);
            }
        }

    // --- w_ih hi-only fragments (FUSED; mg 0 writes) ---
    if constexpr (FUSED) {
        if (mg == 0) {
#pragma unroll
            for (int kt = 0; kt < 6; ++kt)
#pragma unroll
                for (int nt = 0; nt < 3; ++nt) {
                    const int g  = nt * 96 + 8 * wj + (lane >> 2);
                    const int k0 = kt * 16 + (lane & 3) * 2;
                    const float* p = w_ih + (size_t)g * H_ + k0;
                    uint2 v;
                    v.x = pack_h2(__float2half_rn(p[0]), __float2half_rn(p[1]));
                    v.y = pack_h2(__float2half_rn(p[8]), __float2half_rn(p[9]));
                    wpIh[(wj * 18 + kt * 3 + nt) * 32 + lane] = v;
                }
        }
        // combined biases: [0:96) r comb, [96:192) z comb, [192:288) b_in, [288:384) b_hn
        if (tid < 96) {
            bias_s[tid]       = b_ih[tid]       + b_hh[tid];
            bias_s[96 + tid]  = b_ih[96 + tid]  + b_hh[96 + tid];
            bias_s[192 + tid] = b_ih[192 + tid];
            bias_s[288 + tid] = b_hh[192 + tid];
        }
    }

    const int crow = lane >> 2;
    const int jc   = 8 * wj + 2 * (lane & 3);
    const int rbase = mg * 16 + crow;

    // bias regs for !FUSED
    float bcr0 = 0, bcr1 = 0, bcz0 = 0, bcz1 = 0, bin0 = 0, bin1 = 0, bhn0 = 0, bhn1 = 0;
    if constexpr (!FUSED) {
        bcr0 = b_ih[jc]       + b_hh[jc];
        bcr1 = b_ih[jc + 1]   + b_hh[jc + 1];
        bcz0 = b_ih[96 + jc]  + b_hh[96 + jc];
        bcz1 = b_ih[97 + jc]  + b_hh[97 + jc];
        bin0 = b_ih[192 + jc];
        bin1 = b_ih[193 + jc];
        bhn0 = b_hh[192 + jc];
        bhn1 = b_hh[193 + jc];
    }

    // --- init h state ---
    float hold[4];
#pragma unroll
    for (int rh = 0; rh < 2; ++rh) {
        const int row = rbase + rh * 8;
        const float2 v = *(const float2*)&h0[(size_t)(b0 + row) * H_ + jc];
        hold[rh * 2]     = v.x;
        hold[rh * 2 + 1] = v.y;
        *(uint32_t*)&hb[0 * 32 * HP2 + row * HP2 + jc] =
            pack_h2(__float2half_rn(v.x), __float2half_rn(v.y));
    }

    // --- cp.async mapping (per m-group: 192 threads load the group's 16 rows)
    const int gidx    = tid - mg * 384;
    const bool cpon   = (gidx < 192);
    const int cprow   = mg * 16 + gidx / 12;
    const int cpchunk = gidx - (gidx / 12) * 12;
    const uint32_t xbS = (uint32_t)__cvta_generic_to_shared(xb)
                       + (uint32_t)(cprow * HP2 * 2 + cpchunk * 16);
    const uint32_t* xsrc0 = nullptr;
    constexpr uint32_t BUFB = (uint32_t)(32 * HP2 * 2);
    if constexpr (FUSED) {
        if (cpon) {
            xsrc0 = xg + (size_t)(b0 + cprow) * HW + cpchunk * 4;
            cpasync16(xbS, xsrc0);                           // x(0) -> slot0
            cpasync16(xbS + BUFB, xsrc0 + (size_t)B_ * HW);  // x(1) -> slot1
            cpasync_commit();
            cpasync_wait0();
        }
    }
    __syncthreads();

    // ldmatrix per-lane offsets
    const int arow = (lane & 7) + ((lane >> 3) & 1) * 8;
    const int acol = ((lane >> 4) & 1) * 8;
    const uint32_t lofs = (uint32_t)(((mg * 16 + arow) * HP2 + acol) * 2);
    const uint32_t hBase = (uint32_t)__cvta_generic_to_shared(hb) + lofs;
    const uint32_t xBase = (uint32_t)__cvta_generic_to_shared(xb) + lofs;

    const uint32_t wpIhS = (uint32_t)__cvta_generic_to_shared(wpIh)
                         + (uint32_t)(((wj * 18) * 32 + lane) * 8);
    const uint32_t wpLoS = (uint32_t)__cvta_generic_to_shared(wpLo)
                         + (uint32_t)(((wj * 18) * 32 + lane) * 8);
    const uint32_t biasS = (uint32_t)__cvta_generic_to_shared(bias_s);
    const uint32_t combRS = biasS + (uint32_t)(jc * 4);
    const uint32_t bhnS   = combRS + 288 * 4;

    const int barId = 1 + mg;

    float c[3][4], cx[4];
    float g2[3][4], g2x[4];

    if constexpr (FUSED) {
        // prologue: gi(0) -> c, gi(1) -> g2
        const float2 cr = lds2f(combRS);
        const float2 cz = lds2f(combRS + 96 * 4);
        const float2 bn = lds2f(combRS + 192 * 4);
        xgemm2(xBase, xBase + BUFB, wpIhS, cr, cz, bn, c, cx, g2, g2x);

        for (int tt = 0; tt + 1 < T_; tt += 2) {
            // ---- even step tt (accumulators c/cx; hb phase 0 -> 1) ----
            barg(barId);
            if (cpon) {
                const int a = (tt + 2 < T_) ? (tt + 2) : (T_ - 1);
                const int b = (tt + 3 < T_) ? (tt + 3) : (T_ - 1);
                cpasync16(xbS, xsrc0 + (size_t)a * B_ * HW);
                cpasync16(xbS + BUFB, xsrc0 + (size_t)b * B_ * HW);
                cpasync_commit();
            }
            hgemm<true>(hBase, bhi, bloR, wpLoS, c);
            {
                const float2 bhn2 = lds2f(bhnS);
                elem_store<LAST>(c, cx, hold, bhn2, rbase, jc, b0, tt,
                                 hb + 32 * HP2, outg, outf);
            }

            // ---- odd step tt+1 (accumulators g2/g2x; hb phase 1 -> 0) ----
            if (cpon) cpasync_wait0();
            barg(barId);
            hgemm<true>(hBase + BUFB, bhi, bloR, wpLoS, g2);
            {
                const float2 bhn2 = lds2f(bhnS);
                elem_store<LAST>(g2, g2x, hold, bhn2, rbase, jc, b0, tt + 1,
                                 hb, outg, outf);
            }
            // double x-GEMM: gi(tt+2) -> c, gi(tt+3) -> g2
            {
                const float2 cr = lds2f(combRS);
                const float2 cz = lds2f(combRS + 96 * 4);
                const float2 bn = lds2f(combRS + 192 * 4);
                xgemm2(xBase, xBase + BUFB, wpIhS, cr, cz, bn, c, cx, g2, g2x);
            }
        }
        // ---- final even step t = T_-1 = 238 ----
        barg(barId);
        hgemm<true>(hBase, bhi, bloR, wpLoS, c);
        {
            const float2 bhn2 = lds2f(bhnS);
            elem_store<LAST>(c, cx, hold, bhn2, rbase, jc, b0, T_ - 1,
                             hb + 32 * HP2, outg, outf);
        }
    } else {
        for (int t = 0; t < T_; ++t) {
            barg(barId);
#pragma unroll
            for (int q = 0; q < 4; ++q) {
                const bool od = q & 1;
                c[0][q] = od ? bcr1 : bcr0;
                c[1][q] = od ? bcz1 : bcz0;
                c[2][q] = 0.f;
                cx[q]   = od ? bin1 : bin0;
            }
            const uint32_t aH = hBase + (uint32_t)(t & 1) * BUFB;
            hgemm<false>(aH, bhi, bloR, 0u, c);
            elem_store<LAST>(c, cx, hold, make_float2(bhn0, bhn1), rbase, jc, b0, t,
                             hb + (uint32_t)((t & 1) ^ 1) * 32 * HP2, outg, outf);
        }
    }
}

// ---------------------------------------------------------------------------
// fc1 (fp32, tiny)
// ---------------------------------------------------------------------------
__global__ void __launch_bounds__(256, 1)
fc1_kernel(const float* __restrict__ z, const float* __restrict__ c,
           const float* __restrict__ w, const float* __restrict__ bias,
           float* __restrict__ h0out)
{
    extern __shared__ float sm[];
    float* wc_s = sm;
    float* xc_s = wc_s + KC * NFCP;

    const int tid = threadIdx.x;
    const int cx  = tid & 31;
    const int ry  = tid >> 5;
    const int b0  = blockIdx.x * NB_;

    float acc[4][12];
#pragma unroll
    for (int m = 0; m < 4; ++m)
#pragma unroll
        for (int i = 0; i < 12; ++i) acc[m][i] = 0.f;

    for (int kc = 0; kc < KIN; kc += KC) {
        for (int idx = tid; idx < NFC * KC; idx += 256) {
            int g = idx / KC, kk = idx - g * KC;
            wc_s[kk * NFCP + g] = w[(size_t)g * KIN + kc + kk];
        }
        for (int idx = tid; idx < NB_ * KC; idx += 256) {
            int r = idx / KC, kk = idx - r * KC;
            int k = kc + kk;
            float v = (k < 256) ? z[(size_t)(b0 + r) * 256 + k]
                                : c[(size_t)(b0 + r) * 256 + (k - 256)];
            xc_s[kk * HPf + r] = v;
        }
        __syncthreads();
#pragma unroll 4
        for (int kk = 0; kk < KC; ++kk) {
            const float a0 = xc_s[kk * HPf + ry +  0];
            const float a1 = xc_s[kk * HPf + ry +  8];
            const float a2 = xc_s[kk * HPf + ry + 16];
            const float a3 = xc_s[kk * HPf + ry + 24];
            const float* wr = wc_s + kk * NFCP + cx;
#pragma unroll
            for (int i = 0; i < 12; ++i) {
                const float wv = wr[32 * i];
                acc[0][i] = fmaf(a0, wv, acc[0][i]);
                acc[1][i] = fmaf(a1, wv, acc[1][i]);
                acc[2][i] = fmaf(a2, wv, acc[2][i]);
                acc[3][i] = fmaf(a3, wv, acc[3][i]);
            }
        }
        __syncthreads();
    }

#pragma unroll
    for (int m = 0; m < 4; ++m) {
        const int r = b0 + ry + 8 * m;
#pragma unroll
        for (int i = 0; i < 12; ++i) {
            const int g = cx + 32 * i;
            float v = acc[m][i] + bias[g];
            v = (v >= 0.f) ? v : 0.2f * v;
            h0out[(size_t)r * NFC + g] = v;
        }
    }
}

// ---------------------------------------------------------------------------
extern "C" void kernel_launch(void* const* d_in, const int* in_sizes, int n_in,
                              void* d_out, int out_size)
{
    const float* z     = (const float*)d_in[0];
    const float* c     = (const float*)d_in[1];
    const float* fc1_w = (const float*)d_in[2];
    const float* fc1_b = (const float*)d_in[3];
    const float* w_ih  = (const float*)d_in[4];
    const float* w_hh  = (const float*)d_in[5];
    const float* b_ih  = (const float*)d_in[6];
    const float* b_hh  = (const float*)d_in[7];
    float* out = (float*)d_out;

    uint32_t *xA, *xB;
    float *h0Buf;
    cudaGetSymbolAddress((void**)&xA,    g_x16A);
    cudaGetSymbolAddress((void**)&xB,    g_x16B);
    cudaGetSymbolAddress((void**)&h0Buf, g_h0);

    constexpr int NFR = 12 * 18 * 32;
    const size_t smF = (size_t)NFR * 8 + (size_t)NFR * 8
                     + (size_t)(4 * 32 * HP2) * sizeof(__half)
                     + (size_t)384 * sizeof(float);             // 139,136 B
    const size_t sm0 = (size_t)(4 * 32 * HP2) * sizeof(__half); // 13,312 B (hb+xb slot unused)
    const size_t fcSm = (size_t)(KC * NFCP + KC * HPf) * sizeof(float);

    cudaFuncSetAttribute((const void*)scanF<false, false>, cudaFuncAttributeMaxDynamicSharedMemorySize, (int)sm0);
    cudaFuncSetAttribute((const void*)scanF<true,  false>, cudaFuncAttributeMaxDynamicSharedMemorySize, (int)smF);
    cudaFuncSetAttribute((const void*)scanF<true,  true>,  cudaFuncAttributeMaxDynamicSharedMemorySize, (int)smF);
    cudaFuncSetAttribute((const void*)fc1_kernel,           cudaFuncAttributeMaxDynamicSharedMemorySize, (int)fcSm);

    const int nblk = B_ / NB_;  // 128

    fc1_kernel<<<nblk, 256, fcSm>>>(z, c, fc1_w, fc1_b, h0Buf);

    // layer 0: input zeros -> fp16 activations into xA
    scanF<false, false><<<nblk, THR, sm0>>>(w_hh, b_hh, nullptr, b_ih,
                                            h0Buf, nullptr, xA, nullptr);

    // layer 1: xA -> xB
    scanF<true, false><<<nblk, THR, smF>>>(w_hh + 1 * (size_t)G_ * H_, b_hh + 1 * G_,
                                           w_ih + 1 * (size_t)G_ * H_, b_ih + 1 * G_,
                                           h0Buf + 1 * (size_t)B_ * H_, xA, xB, nullptr);
    // layer 2: xB -> xA
    scanF<true, false><<<nblk, THR, smF>>>(w_hh + 2 * (size_t)G_ * H_, b_hh + 2 * G_,
                                           w_ih + 2 * (size_t)G_ * H_, b_ih + 2 * G_,
                                           h0Buf + 2 * (size_t)B_ * H_, xB, xA, nullptr);
    // layer 3: xA -> out [B,H,T] directly (transpose folded in)
    scanF<true, true><<<nblk, THR, smF>>>(w_hh + 3 * (size_t)G_ * H_, b_hh + 3 * G_,
                                          w_ih + 3 * (size_t)G_ * H_, b_ih + 3 * G_,
                                          h0Buf + 3 * (size_t)B_ * H_, xA, nullptr, out);
}

// round 16
// speedup vs baseline: 1.4549x; 1.0857x over previous
#include <cuda_runtime.h>
#include <cuda_fp16.h>
#include <cstdint>
#include <cstddef>

// ---------------------------------------------------------------------------
constexpr int H_  = 96;
constexpr int G_  = 288;
constexpr int T_  = 239;
constexpr int B_  = 4096;
constexpr int NB_ = 32;
constexpr int HW  = 48;    // H/2 packed words per row

constexpr int HP2 = 104;   // fp16 pitch for A (h/x) ldmatrix tiles
constexpr int THR = 768;   // 24 warps: 12 j-groups x 2 m-groups

constexpr int KIN  = 512;
constexpr int NFC  = 384;
constexpr int NFCP = 385;
constexpr int KC   = 64;
constexpr int HPf  = 33;

constexpr size_t SZ_X16 = (size_t)T_ * B_ * HW;
constexpr size_t SZ_H0  = (size_t)B_ * NFC;

__device__ uint32_t g_x16A[SZ_X16];
__device__ uint32_t g_x16B[SZ_X16];
__device__ float    g_h0  [SZ_H0];

// ---------------------------------------------------------------------------
__device__ __forceinline__ float ex2f(float x) {
    float y; asm("ex2.approx.f32 %0, %1;" : "=f"(y) : "f"(x)); return y;
}
__device__ __forceinline__ float rcpf(float x) {
    float y; asm("rcp.approx.f32 %0, %1;" : "=f"(y) : "f"(x)); return y;
}
constexpr float L2E = 1.4426950408889634f;

__device__ __forceinline__ uint32_t pack_h2(__half a, __half b) {
    return (uint32_t)__half_as_ushort(a) | ((uint32_t)__half_as_ushort(b) << 16);
}
__device__ __forceinline__ void split2h(float x, __half& h, __half& l) {
    h = __float2half_rn(x);
    l = __float2half_rn(x - __half2float(h));
}

__device__ __forceinline__ void mma16816(float c[4], const uint32_t a[4],
                                         const uint32_t b0, const uint32_t b1) {
    asm volatile(
        "mma.sync.aligned.m16n8k16.row.col.f32.f16.f16.f32 "
        "{%0,%1,%2,%3}, {%4,%5,%6,%7}, {%8,%9}, {%0,%1,%2,%3};"
        : "+f"(c[0]), "+f"(c[1]), "+f"(c[2]), "+f"(c[3])
        : "r"(a[0]), "r"(a[1]), "r"(a[2]), "r"(a[3]), "r"(b0), "r"(b1));
}
__device__ __forceinline__ void ldsm4(uint32_t r[4], uint32_t addr) {
    asm volatile("ldmatrix.sync.aligned.m8n8.x4.shared.b16 {%0,%1,%2,%3}, [%4];"
                 : "=r"(r[0]), "=r"(r[1]), "=r"(r[2]), "=r"(r[3]) : "r"(addr));
}
__device__ __forceinline__ void lds2(uint32_t addr, uint32_t& x, uint32_t& y) {
    asm volatile("ld.shared.v2.u32 {%0,%1}, [%2];" : "=r"(x), "=r"(y) : "r"(addr));
}
__device__ __forceinline__ float2 lds2f(uint32_t addr) {
    float2 v;
    asm volatile("ld.shared.v2.f32 {%0,%1}, [%2];" : "=f"(v.x), "=f"(v.y) : "r"(addr));
    return v;
}
__device__ __forceinline__ void cpasync16(uint32_t smem_addr, const void* gptr) {
    asm volatile("cp.async.cg.shared.global [%0], [%1], 16;" :: "r"(smem_addr), "l"(gptr));
}
__device__ __forceinline__ void cpasync_commit() {
    asm volatile("cp.async.commit_group;" ::: "memory");
}
__device__ __forceinline__ void cpasync_wait0() {
    asm volatile("cp.async.wait_group 0;" ::: "memory");
}
__device__ __forceinline__ void barg(int id) {
    asm volatile("bar.sync %0, 384;" :: "r"(id) : "memory");
}

// ---------------------------------------------------------------------------
// h-GEMM: r,z gates single-term (hi regs); n gate 2-term (hi regs + lo from
// smem when FUSED / regs when not).
// ---------------------------------------------------------------------------
template <bool FUSED>
__device__ __forceinline__ void hgemm(uint32_t aH,
                                      const uint32_t (&bhi)[6][3][2],
                                      const uint32_t (&bloN)[6][2],
                                      uint32_t wpLoS, float (&c)[3][4]) {
#pragma unroll
    for (int kt = 0; kt < 6; ++kt) {
        uint32_t ah[4];
        ldsm4(ah, aH + (uint32_t)(kt * 32));
        mma16816(c[0], ah, bhi[kt][0][0], bhi[kt][0][1]);
        mma16816(c[1], ah, bhi[kt][1][0], bhi[kt][1][1]);
        mma16816(c[2], ah, bhi[kt][2][0], bhi[kt][2][1]);
        if constexpr (FUSED) {
            uint32_t lx, ly;
            lds2(wpLoS + (uint32_t)(kt * 256), lx, ly);
            mma16816(c[2], ah, lx, ly);
        } else {
            mma16816(c[2], ah, bloN[kt][0], bloN[kt][1]);
        }
    }
}

// ---------------------------------------------------------------------------
// Double x-GEMM: gi(even t) -> c/cx and gi(odd t) -> g2/g2x, sharing each
// w_ih fragment load. Accumulators initialized with folded biases.
// ---------------------------------------------------------------------------
__device__ __forceinline__ void xgemm2(uint32_t aX0, uint32_t aX1, uint32_t wpIhS,
                                       float2 cr, float2 cz, float2 bn,
                                       float (&c)[3][4], float (&cx)[4],
                                       float (&g2)[3][4], float (&g2x)[4]) {
#pragma unroll
    for (int q = 0; q < 4; ++q) {
        const bool od = q & 1;
        const float r0 = od ? cr.y : cr.x;
        const float z0 = od ? cz.y : cz.x;
        const float n0 = od ? bn.y : bn.x;
        c[0][q] = r0;  c[1][q] = z0;  c[2][q] = 0.f;  cx[q] = n0;
        g2[0][q] = r0; g2[1][q] = z0; g2[2][q] = 0.f; g2x[q] = n0;
    }
#pragma unroll
    for (int kt = 0; kt < 6; ++kt) {
        uint32_t x0[4], x1[4];
        ldsm4(x0, aX0 + (uint32_t)(kt * 32));
        ldsm4(x1, aX1 + (uint32_t)(kt * 32));
        uint32_t v0x, v0y, v1x, v1y, v2x, v2y;
        lds2(wpIhS + (uint32_t)((kt * 3 + 0) * 256), v0x, v0y);
        lds2(wpIhS + (uint32_t)((kt * 3 + 1) * 256), v1x, v1y);
        lds2(wpIhS + (uint32_t)((kt * 3 + 2) * 256), v2x, v2y);
        mma16816(c[0],  x0, v0x, v0y);
        mma16816(c[1],  x0, v1x, v1y);
        mma16816(cx,    x0, v2x, v2y);
        mma16816(g2[0], x1, v0x, v0y);
        mma16816(g2[1], x1, v1x, v1y);
        mma16816(g2x,   x1, v2x, v2y);
    }
}

// ---------------------------------------------------------------------------
// Elementwise + state/output stores for one step.
// ---------------------------------------------------------------------------
template <bool LAST>
__device__ __forceinline__ void elem_store(const float (&c)[3][4], const float (&cx)[4],
                                           float (&hold)[4], float2 bhn2,
                                           int rbase, int jc, int b0, int t,
                                           __half* hbw,
                                           uint32_t* __restrict__ outg,
                                           float* __restrict__ outf) {
#pragma unroll
    for (int rh = 0; rh < 2; ++rh) {
        const int row = rbase + rh * 8;
        float hn2[2];
#pragma unroll
        for (int col = 0; col < 2; ++col) {
            const int q = rh * 2 + col;
            const float bhn = col ? bhn2.y : bhn2.x;
            const float ar = c[0][q];
            const float az = c[1][q];
            const float u  = 1.f + ex2f(-L2E * ar);
            const float v  = 1.f + ex2f(-L2E * az);
            const float wv = rcpf(u * v);
            const float rg = v * wv;              // sigmoid(ar)
            const float zg = u * wv;              // sigmoid(az)
            const float na = cx[q] + rg * (c[2][q] + bhn);
            const float s  = 1.f + ex2f(-2.f * L2E * na);
            const float ng = 2.f * rcpf(s) - 1.f; // tanh(na)
            const float hv = ng + zg * (hold[q] - ng);
            hold[q] = hv;
            hn2[col] = hv;
        }
        const uint32_t ph = pack_h2(__float2half_rn(hn2[0]), __float2half_rn(hn2[1]));
        *(uint32_t*)&hbw[row * HP2 + jc] = ph;
        if constexpr (LAST) {
            const int ob = ((b0 + row) * H_ + jc) * T_ + t;
            outf[ob]      = hn2[0];
            outf[ob + T_] = hn2[1];
        } else {
            outg[(size_t)(t * B_ + b0 + row) * HW + (jc >> 1)] = ph;
        }
    }
}

// ---------------------------------------------------------------------------
// Fused GRU scan, 24 warps (m-split), per-group named barriers, unroll-2
// with shared x-weight fragment loads. h r,z single-term; h n-gate 2-term.
// ---------------------------------------------------------------------------
template <bool FUSED, bool LAST>
__global__ void __launch_bounds__(THR, 1)
scanF(const float* __restrict__ w_hh, const float* __restrict__ b_hh,
      const float* __restrict__ w_ih, const float* __restrict__ b_ih,
      const float* __restrict__ h0,   const uint32_t* __restrict__ xg,
      uint32_t* __restrict__ outg,    float* __restrict__ outf)
{
    extern __shared__ __align__(16) char smraw[];
    constexpr int NFI = 12 * 18 * 32;   // w_ih frags (uint2)
    constexpr int NFL = 12 * 6 * 32;    // w_hh-lo n-gate frags (uint2)
    uint2*  wpIh = (uint2*)smraw;
    uint2*  wpLo = (uint2*)(smraw + (FUSED ? NFI * 8 : 0));
    __half* hb   = (__half*)((char*)wpLo + (FUSED ? NFL * 8 : 0));
    __half* xb   = hb + 2 * 32 * HP2;
    float* bias_s = (float*)(xb + (FUSED ? 2 * 32 * HP2 : 0));   // 384 floats (FUSED)

    const int tid  = threadIdx.x;
    const int lane = tid & 31;
    const int w    = tid >> 5;          // 0..23
    const int wj   = w % 12;
    const int mg   = w / 12;
    const int b0   = blockIdx.x * NB_;

    // --- w_hh: hi -> regs (all gates); n-gate lo -> smem (FUSED) / regs ---
    uint32_t bhi[6][3][2];
    uint32_t bloN[6][2];
#pragma unroll
    for (int kt = 0; kt < 6; ++kt)
#pragma unroll
        for (int nt = 0; nt < 3; ++nt) {
            const int g  = nt * 96 + 8 * wj + (lane >> 2);
            const int k0 = kt * 16 + (lane & 3) * 2;
            const float* p = w_hh + (size_t)g * H_ + k0;
            float w0 = p[0], w1 = p[1], w2 = p[8], w3 = p[9];
            __half h0b, h1b, h2b, h3b, l0b, l1b, l2b, l3b;
            split2h(w0, h0b, l0b); split2h(w1, h1b, l1b);
            split2h(w2, h2b, l2b); split2h(w3, h3b, l3b);
            bhi[kt][nt][0] = pack_h2(h0b, h1b);
            bhi[kt][nt][1] = pack_h2(h2b, h3b);
            if (nt == 2) {
                if constexpr (FUSED) {
                    if (mg == 0) {
                        uint2 lv;
                        lv.x = pack_h2(l0b, l1b);
                        lv.y = pack_h2(l2b, l3b);
                        wpLo[(wj * 6 + kt) * 32 + lane] = lv;
                    }
                } else {
                    bloN[kt][0] = pack_h2(l0b, l1b);
                    bloN[kt][1] = pack_h2(l2b, l3b);
                }
            }
        }

    // --- w_ih hi-only fragments (FUSED; mg 0 writes) ---
    if constexpr (FUSED) {
        if (mg == 0) {
#pragma unroll
            for (int kt = 0; kt < 6; ++kt)
#pragma unroll
                for (int nt = 0; nt < 3; ++nt) {
                    const int g  = nt * 96 + 8 * wj + (lane >> 2);
                    const int k0 = kt * 16 + (lane & 3) * 2;
                    const float* p = w_ih + (size_t)g * H_ + k0;
                    uint2 v;
                    v.x = pack_h2(__float2half_rn(p[0]), __float2half_rn(p[1]));
                    v.y = pack_h2(__float2half_rn(p[8]), __float2half_rn(p[9]));
                    wpIh[(wj * 18 + kt * 3 + nt) * 32 + lane] = v;
                }
        }
        // combined biases: [0:96) r, [96:192) z, [192:288) b_in, [288:384) b_hn
        if (tid < 96) {
            bias_s[tid]       = b_ih[tid]       + b_hh[tid];
            bias_s[96 + tid]  = b_ih[96 + tid]  + b_hh[96 + tid];
            bias_s[192 + tid] = b_ih[192 + tid];
            bias_s[288 + tid] = b_hh[192 + tid];
        }
    }

    const int crow = lane >> 2;
    const int jc   = 8 * wj + 2 * (lane & 3);
    const int rbase = mg * 16 + crow;

    // bias regs for !FUSED
    float bcr0 = 0, bcr1 = 0, bcz0 = 0, bcz1 = 0, bin0 = 0, bin1 = 0, bhn0 = 0, bhn1 = 0;
    if constexpr (!FUSED) {
        bcr0 = b_ih[jc]       + b_hh[jc];
        bcr1 = b_ih[jc + 1]   + b_hh[jc + 1];
        bcz0 = b_ih[96 + jc]  + b_hh[96 + jc];
        bcz1 = b_ih[97 + jc]  + b_hh[97 + jc];
        bin0 = b_ih[192 + jc];
        bin1 = b_ih[193 + jc];
        bhn0 = b_hh[192 + jc];
        bhn1 = b_hh[193 + jc];
    }

    // --- init h state ---
    float hold[4];
#pragma unroll
    for (int rh = 0; rh < 2; ++rh) {
        const int row = rbase + rh * 8;
        const float2 v = *(const float2*)&h0[(size_t)(b0 + row) * H_ + jc];
        hold[rh * 2]     = v.x;
        hold[rh * 2 + 1] = v.y;
        *(uint32_t*)&hb[0 * 32 * HP2 + row * HP2 + jc] =
            pack_h2(__float2half_rn(v.x), __float2half_rn(v.y));
    }

    // --- cp.async mapping (per m-group: 192 threads load the group's 16 rows)
    const int gidx    = tid - mg * 384;
    const bool cpon   = (gidx < 192);
    const int cprow   = mg * 16 + gidx / 12;
    const int cpchunk = gidx - (gidx / 12) * 12;
    const uint32_t xbS = (uint32_t)__cvta_generic_to_shared(xb)
                       + (uint32_t)(cprow * HP2 * 2 + cpchunk * 16);
    const uint32_t* xsrc0 = nullptr;
    constexpr uint32_t BUFB = (uint32_t)(32 * HP2 * 2);
    if constexpr (FUSED) {
        if (cpon) {
            xsrc0 = xg + (size_t)(b0 + cprow) * HW + cpchunk * 4;
            cpasync16(xbS, xsrc0);                           // x(0) -> slot0
            cpasync16(xbS + BUFB, xsrc0 + (size_t)B_ * HW);  // x(1) -> slot1
            cpasync_commit();
            cpasync_wait0();
        }
    }
    __syncthreads();

    // ldmatrix per-lane offsets
    const int arow = (lane & 7) + ((lane >> 3) & 1) * 8;
    const int acol = ((lane >> 4) & 1) * 8;
    const uint32_t lofs = (uint32_t)(((mg * 16 + arow) * HP2 + acol) * 2);
    const uint32_t hBase = (uint32_t)__cvta_generic_to_shared(hb) + lofs;
    const uint32_t xBase = (uint32_t)__cvta_generic_to_shared(xb) + lofs;

    const uint32_t wpIhS = (uint32_t)__cvta_generic_to_shared(wpIh)
                         + (uint32_t)(((wj * 18) * 32 + lane) * 8);
    const uint32_t wpLoS = (uint32_t)__cvta_generic_to_shared(wpLo)
                         + (uint32_t)(((wj * 6) * 32 + lane) * 8);
    const uint32_t biasS = (uint32_t)__cvta_generic_to_shared(bias_s);
    const uint32_t combRS = biasS + (uint32_t)(jc * 4);
    const uint32_t bhnS   = combRS + 288 * 4;

    const int barId = 1 + mg;

    float c[3][4], cx[4];
    float g2[3][4], g2x[4];

    if constexpr (FUSED) {
        // prologue: gi(0) -> c, gi(1) -> g2
        const float2 cr = lds2f(combRS);
        const float2 cz = lds2f(combRS + 96 * 4);
        const float2 bn = lds2f(combRS + 192 * 4);
        xgemm2(xBase, xBase + BUFB, wpIhS, cr, cz, bn, c, cx, g2, g2x);

        for (int tt = 0; tt + 1 < T_; tt += 2) {
            // ---- even step tt (accumulators c/cx; hb phase 0 -> 1) ----
            barg(barId);
            if (cpon) {
                const int a = (tt + 2 < T_) ? (tt + 2) : (T_ - 1);
                const int b = (tt + 3 < T_) ? (tt + 3) : (T_ - 1);
                cpasync16(xbS, xsrc0 + (size_t)a * B_ * HW);
                cpasync16(xbS + BUFB, xsrc0 + (size_t)b * B_ * HW);
                cpasync_commit();
            }
            hgemm<true>(hBase, bhi, bloN, wpLoS, c);
            {
                const float2 bhn2 = lds2f(bhnS);
                elem_store<LAST>(c, cx, hold, bhn2, rbase, jc, b0, tt,
                                 hb + 32 * HP2, outg, outf);
            }

            // ---- odd step tt+1 (accumulators g2/g2x; hb phase 1 -> 0) ----
            if (cpon) cpasync_wait0();
            barg(barId);
            hgemm<true>(hBase + BUFB, bhi, bloN, wpLoS, g2);
            {
                const float2 bhn2 = lds2f(bhnS);
                elem_store<LAST>(g2, g2x, hold, bhn2, rbase, jc, b0, tt + 1,
                                 hb, outg, outf);
            }
            // double x-GEMM: gi(tt+2) -> c, gi(tt+3) -> g2
            {
                const float2 cr = lds2f(combRS);
                const float2 cz = lds2f(combRS + 96 * 4);
                const float2 bn = lds2f(combRS + 192 * 4);
                xgemm2(xBase, xBase + BUFB, wpIhS, cr, cz, bn, c, cx, g2, g2x);
            }
        }
        // ---- final even step t = T_-1 ----
        barg(barId);
        hgemm<true>(hBase, bhi, bloN, wpLoS, c);
        {
            const float2 bhn2 = lds2f(bhnS);
            elem_store<LAST>(c, cx, hold, bhn2, rbase, jc, b0, T_ - 1,
                             hb + 32 * HP2, outg, outf);
        }
    } else {
        for (int t = 0; t < T_; ++t) {
            barg(barId);
#pragma unroll
            for (int q = 0; q < 4; ++q) {
                const bool od = q & 1;
                c[0][q] = od ? bcr1 : bcr0;
                c[1][q] = od ? bcz1 : bcz0;
                c[2][q] = 0.f;
                cx[q]   = od ? bin1 : bin0;
            }
            const uint32_t aH = hBase + (uint32_t)(t & 1) * BUFB;
            hgemm<false>(aH, bhi, bloN, 0u, c);
            elem_store<LAST>(c, cx, hold, make_float2(bhn0, bhn1), rbase, jc, b0, t,
                             hb + (uint32_t)((t & 1) ^ 1) * 32 * HP2, outg, outf);
        }
    }
}

// ---------------------------------------------------------------------------
// fc1 (fp32, tiny)
// ---------------------------------------------------------------------------
__global__ void __launch_bounds__(256, 1)
fc1_kernel(const float* __restrict__ z, const float* __restrict__ c,
           const float* __restrict__ w, const float* __restrict__ bias,
           float* __restrict__ h0out)
{
    extern __shared__ float sm[];
    float* wc_s = sm;
    float* xc_s = wc_s + KC * NFCP;

    const int tid = threadIdx.x;
    const int cx  = tid & 31;
    const int ry  = tid >> 5;
    const int b0  = blockIdx.x * NB_;

    float acc[4][12];
#pragma unroll
    for (int m = 0; m < 4; ++m)
#pragma unroll
        for (int i = 0; i < 12; ++i) acc[m][i] = 0.f;

    for (int kc = 0; kc < KIN; kc += KC) {
        for (int idx = tid; idx < NFC * KC; idx += 256) {
            int g = idx / KC, kk = idx - g * KC;
            wc_s[kk * NFCP + g] = w[(size_t)g * KIN + kc + kk];
        }
        for (int idx = tid; idx < NB_ * KC; idx += 256) {
            int r = idx / KC, kk = idx - r * KC;
            int k = kc + kk;
            float v = (k < 256) ? z[(size_t)(b0 + r) * 256 + k]
                                : c[(size_t)(b0 + r) * 256 + (k - 256)];
            xc_s[kk * HPf + r] = v;
        }
        __syncthreads();
#pragma unroll 4
        for (int kk = 0; kk < KC; ++kk) {
            const float a0 = xc_s[kk * HPf + ry +  0];
            const float a1 = xc_s[kk * HPf + ry +  8];
            const float a2 = xc_s[kk * HPf + ry + 16];
            const float a3 = xc_s[kk * HPf + ry + 24];
            const float* wr = wc_s + kk * NFCP + cx;
#pragma unroll
            for (int i = 0; i < 12; ++i) {
                const float wv = wr[32 * i];
                acc[0][i] = fmaf(a0, wv, acc[0][i]);
                acc[1][i] = fmaf(a1, wv, acc[1][i]);
                acc[2][i] = fmaf(a2, wv, acc[2][i]);
                acc[3][i] = fmaf(a3, wv, acc[3][i]);
            }
        }
        __syncthreads();
    }

#pragma unroll
    for (int m = 0; m < 4; ++m) {
        const int r = b0 + ry + 8 * m;
#pragma unroll
        for (int i = 0; i < 12; ++i) {
            const int g = cx + 32 * i;
            float v = acc[m][i] + bias[g];
            v = (v >= 0.f) ? v : 0.2f * v;
            h0out[(size_t)r * NFC + g] = v;
        }
    }
}

// ---------------------------------------------------------------------------
extern "C" void kernel_launch(void* const* d_in, const int* in_sizes, int n_in,
                              void* d_out, int out_size)
{
    const float* z     = (const float*)d_in[0];
    const float* c     = (const float*)d_in[1];
    const float* fc1_w = (const float*)d_in[2];
    const float* fc1_b = (const float*)d_in[3];
    const float* w_ih  = (const float*)d_in[4];
    const float* w_hh  = (const float*)d_in[5];
    const float* b_ih  = (const float*)d_in[6];
    const float* b_hh  = (const float*)d_in[7];
    float* out = (float*)d_out;

    uint32_t *xA, *xB;
    float *h0Buf;
    cudaGetSymbolAddress((void**)&xA,    g_x16A);
    cudaGetSymbolAddress((void**)&xB,    g_x16B);
    cudaGetSymbolAddress((void**)&h0Buf, g_h0);

    constexpr int NFI = 12 * 18 * 32;
    constexpr int NFL = 12 * 6 * 32;
    const size_t smF = (size_t)NFI * 8 + (size_t)NFL * 8
                     + (size_t)(4 * 32 * HP2) * sizeof(__half)
                     + (size_t)384 * sizeof(float);             // 101,888 B
    const size_t sm0 = (size_t)(4 * 32 * HP2) * sizeof(__half); // 13,312 B
    const size_t fcSm = (size_t)(KC * NFCP + KC * HPf) * sizeof(float);

    cudaFuncSetAttribute((const void*)scanF<false, false>, cudaFuncAttributeMaxDynamicSharedMemorySize, (int)sm0);
    cudaFuncSetAttribute((const void*)scanF<true,  false>, cudaFuncAttributeMaxDynamicSharedMemorySize, (int)smF);
    cudaFuncSetAttribute((const void*)scanF<true,  true>,  cudaFuncAttributeMaxDynamicSharedMemorySize, (int)smF);
    cudaFuncSetAttribute((const void*)fc1_kernel,           cudaFuncAttributeMaxDynamicSharedMemorySize, (int)fcSm);

    const int nblk = B_ / NB_;  // 128

    fc1_kernel<<<nblk, 256, fcSm>>>(z, c, fc1_w, fc1_b, h0Buf);

    // layer 0: input zeros -> fp16 activations into xA
    scanF<false, false><<<nblk, THR, sm0>>>(w_hh, b_hh, nullptr, b_ih,
                                            h0Buf, nullptr, xA, nullptr);

    // layer 1: xA -> xB
    scanF<true, false><<<nblk, THR, smF>>>(w_hh + 1 * (size_t)G_ * H_, b_hh + 1 * G_,
                                           w_ih + 1 * (size_t)G_ * H_, b_ih + 1 * G_,
                                           h0Buf + 1 * (size_t)B_ * H_, xA, xB, nullptr);
    // layer 2: xB -> xA
    scanF<true, false><<<nblk, THR, smF>>>(w_hh + 2 * (size_t)G_ * H_, b_hh + 2 * G_,
                                           w_ih + 2 * (size_t)G_ * H_, b_ih + 2 * G_,
                                           h0Buf + 2 * (size_t)B_ * H_, xB, xA, nullptr);
    // layer 3: xA -> out [B,H,T] directly (transpose folded in)
    scanF<true, true><<<nblk, THR, smF>>>(w_hh + 3 * (size_t)G_ * H_, b_hh + 3 * G_,
                                          w_ih + 3 * (size_t)G_ * H_, b_ih + 3 * G_,
                                          h0Buf + 3 * (size_t)B_ * H_, xA, nullptr, out);
}

// round 17
// speedup vs baseline: 1.8571x; 1.2764x over previous
#include <cuda_runtime.h>
#include <cuda_fp16.h>
#include <cstdint>
#include <cstddef>

// ---------------------------------------------------------------------------
constexpr int H_  = 96;
constexpr int G_  = 288;
constexpr int T_  = 239;
constexpr int B_  = 4096;
constexpr int NB_ = 32;
constexpr int HW  = 48;    // H/2 packed words per row

constexpr int HP2 = 104;   // fp16 pitch for A (h/x) ldmatrix tiles
constexpr int THR = 768;   // 24 warps: 12 j-groups x 2 m-groups

constexpr int KIN  = 512;
constexpr int NFC  = 384;
constexpr int NFCP = 385;
constexpr int KC   = 64;
constexpr int HPf  = 33;

constexpr size_t SZ_X16 = (size_t)T_ * B_ * HW;
constexpr size_t SZ_H0  = (size_t)B_ * NFC;

__device__ uint32_t g_x16A[SZ_X16];
__device__ uint32_t g_x16B[SZ_X16];
__device__ float    g_h0  [SZ_H0];

// ---------------------------------------------------------------------------
__device__ __forceinline__ float ex2f(float x) {
    float y; asm("ex2.approx.f32 %0, %1;" : "=f"(y) : "f"(x)); return y;
}
__device__ __forceinline__ float rcpf(float x) {
    float y; asm("rcp.approx.f32 %0, %1;" : "=f"(y) : "f"(x)); return y;
}
constexpr float L2E = 1.4426950408889634f;

__device__ __forceinline__ uint32_t pack_h2(__half a, __half b) {
    return (uint32_t)__half_as_ushort(a) | ((uint32_t)__half_as_ushort(b) << 16);
}

__device__ __forceinline__ void mma16816(float c[4], const uint32_t a[4],
                                         const uint32_t b0, const uint32_t b1) {
    asm volatile(
        "mma.sync.aligned.m16n8k16.row.col.f32.f16.f16.f32 "
        "{%0,%1,%2,%3}, {%4,%5,%6,%7}, {%8,%9}, {%0,%1,%2,%3};"
        : "+f"(c[0]), "+f"(c[1]), "+f"(c[2]), "+f"(c[3])
        : "r"(a[0]), "r"(a[1]), "r"(a[2]), "r"(a[3]), "r"(b0), "r"(b1));
}
__device__ __forceinline__ void ldsm4(uint32_t r[4], uint32_t addr) {
    asm volatile("ldmatrix.sync.aligned.m8n8.x4.shared.b16 {%0,%1,%2,%3}, [%4];"
                 : "=r"(r[0]), "=r"(r[1]), "=r"(r[2]), "=r"(r[3]) : "r"(addr));
}
__device__ __forceinline__ void lds2(uint32_t addr, uint32_t& x, uint32_t& y) {
    asm volatile("ld.shared.v2.u32 {%0,%1}, [%2];" : "=r"(x), "=r"(y) : "r"(addr));
}
__device__ __forceinline__ float2 lds2f(uint32_t addr) {
    float2 v;
    asm volatile("ld.shared.v2.f32 {%0,%1}, [%2];" : "=f"(v.x), "=f"(v.y) : "r"(addr));
    return v;
}
__device__ __forceinline__ void cpasync16(uint32_t smem_addr, const void* gptr) {
    asm volatile("cp.async.cg.shared.global [%0], [%1], 16;" :: "r"(smem_addr), "l"(gptr));
}
__device__ __forceinline__ void cpasync_commit() {
    asm volatile("cp.async.commit_group;" ::: "memory");
}
__device__ __forceinline__ void cpasync_wait0() {
    asm volatile("cp.async.wait_group 0;" ::: "memory");
}
__device__ __forceinline__ void barg(int id) {
    asm volatile("bar.sync %0, 384;" :: "r"(id) : "memory");
}

// ---------------------------------------------------------------------------
// h-GEMM: all gates single-term fp16 (hi fragments in registers).
// ---------------------------------------------------------------------------
__device__ __forceinline__ void hgemm(uint32_t aH,
                                      const uint32_t (&bhi)[6][3][2],
                                      float (&c)[3][4]) {
#pragma unroll
    for (int kt = 0; kt < 6; ++kt) {
        uint32_t ah[4];
        ldsm4(ah, aH + (uint32_t)(kt * 32));
        mma16816(c[0], ah, bhi[kt][0][0], bhi[kt][0][1]);
        mma16816(c[1], ah, bhi[kt][1][0], bhi[kt][1][1]);
        mma16816(c[2], ah, bhi[kt][2][0], bhi[kt][2][1]);
    }
}

// ---------------------------------------------------------------------------
// Double x-GEMM: gi(even t) -> c/cx and gi(odd t) -> g2/g2x, sharing each
// w_ih fragment load. Accumulators initialized with folded biases.
// ---------------------------------------------------------------------------
__device__ __forceinline__ void xgemm2(uint32_t aX0, uint32_t aX1, uint32_t wpIhS,
                                       float2 cr, float2 cz, float2 bn,
                                       float (&c)[3][4], float (&cx)[4],
                                       float (&g2)[3][4], float (&g2x)[4]) {
#pragma unroll
    for (int q = 0; q < 4; ++q) {
        const bool od = q & 1;
        const float r0 = od ? cr.y : cr.x;
        const float z0 = od ? cz.y : cz.x;
        const float n0 = od ? bn.y : bn.x;
        c[0][q] = r0;  c[1][q] = z0;  c[2][q] = 0.f;  cx[q] = n0;
        g2[0][q] = r0; g2[1][q] = z0; g2[2][q] = 0.f; g2x[q] = n0;
    }
#pragma unroll
    for (int kt = 0; kt < 6; ++kt) {
        uint32_t x0[4], x1[4];
        ldsm4(x0, aX0 + (uint32_t)(kt * 32));
        ldsm4(x1, aX1 + (uint32_t)(kt * 32));
        uint32_t v0x, v0y, v1x, v1y, v2x, v2y;
        lds2(wpIhS + (uint32_t)((kt * 3 + 0) * 256), v0x, v0y);
        lds2(wpIhS + (uint32_t)((kt * 3 + 1) * 256), v1x, v1y);
        lds2(wpIhS + (uint32_t)((kt * 3 + 2) * 256), v2x, v2y);
        mma16816(c[0],  x0, v0x, v0y);
        mma16816(c[1],  x0, v1x, v1y);
        mma16816(cx,    x0, v2x, v2y);
        mma16816(g2[0], x1, v0x, v0y);
        mma16816(g2[1], x1, v1x, v1y);
        mma16816(g2x,   x1, v2x, v2y);
    }
}

// ---------------------------------------------------------------------------
// Elementwise + state/output stores for one step (all outputs packed fp16).
// ---------------------------------------------------------------------------
__device__ __forceinline__ void elem_store(const float (&c)[3][4], const float (&cx)[4],
                                           float (&hold)[4], float2 bhn2,
                                           int rbase, int jc, int b0, int t,
                                           __half* hbw,
                                           uint32_t* __restrict__ outg) {
#pragma unroll
    for (int rh = 0; rh < 2; ++rh) {
        const int row = rbase + rh * 8;
        float hn2[2];
#pragma unroll
        for (int col = 0; col < 2; ++col) {
            const int q = rh * 2 + col;
            const float bhn = col ? bhn2.y : bhn2.x;
            const float ar = c[0][q];
            const float az = c[1][q];
            const float u  = 1.f + ex2f(-L2E * ar);
            const float v  = 1.f + ex2f(-L2E * az);
            const float wv = rcpf(u * v);
            const float rg = v * wv;              // sigmoid(ar)
            const float zg = u * wv;              // sigmoid(az)
            const float na = cx[q] + rg * (c[2][q] + bhn);
            const float s  = 1.f + ex2f(-2.f * L2E * na);
            const float ng = 2.f * rcpf(s) - 1.f; // tanh(na)
            const float hv = ng + zg * (hold[q] - ng);
            hold[q] = hv;
            hn2[col] = hv;
        }
        const uint32_t ph = pack_h2(__float2half_rn(hn2[0]), __float2half_rn(hn2[1]));
        *(uint32_t*)&hbw[row * HP2 + jc] = ph;
        outg[(size_t)(t * B_ + b0 + row) * HW + (jc >> 1)] = ph;
    }
}

// ---------------------------------------------------------------------------
// Fused GRU scan, 24 warps (m-split), per-group named barriers, unroll-2
// with shared x-weight fragment loads. ALL weights single-term fp16.
// ---------------------------------------------------------------------------
template <bool FUSED>
__global__ void __launch_bounds__(THR, 1)
scanF(const float* __restrict__ w_hh, const float* __restrict__ b_hh,
      const float* __restrict__ w_ih, const float* __restrict__ b_ih,
      const float* __restrict__ h0,   const uint32_t* __restrict__ xg,
      uint32_t* __restrict__ outg)
{
    extern __shared__ __align__(16) char smraw[];
    constexpr int NFI = 12 * 18 * 32;   // w_ih frags (uint2)
    uint2*  wpIh = (uint2*)smraw;
    __half* hb   = (__half*)(smraw + (FUSED ? NFI * 8 : 0));
    __half* xb   = hb + 2 * 32 * HP2;
    float* bias_s = (float*)(xb + (FUSED ? 2 * 32 * HP2 : 0));   // 384 floats (FUSED)

    const int tid  = threadIdx.x;
    const int lane = tid & 31;
    const int w    = tid >> 5;          // 0..23
    const int wj   = w % 12;
    const int mg   = w / 12;
    const int b0   = blockIdx.x * NB_;

    // --- w_hh hi fragments -> regs (single-term, all gates) ---
    uint32_t bhi[6][3][2];
#pragma unroll
    for (int kt = 0; kt < 6; ++kt)
#pragma unroll
        for (int nt = 0; nt < 3; ++nt) {
            const int g  = nt * 96 + 8 * wj + (lane >> 2);
            const int k0 = kt * 16 + (lane & 3) * 2;
            const float* p = w_hh + (size_t)g * H_ + k0;
            bhi[kt][nt][0] = pack_h2(__float2half_rn(p[0]), __float2half_rn(p[1]));
            bhi[kt][nt][1] = pack_h2(__float2half_rn(p[8]), __float2half_rn(p[9]));
        }

    // --- w_ih hi-only fragments (FUSED; mg 0 writes) ---
    if constexpr (FUSED) {
        if (mg == 0) {
#pragma unroll
            for (int kt = 0; kt < 6; ++kt)
#pragma unroll
                for (int nt = 0; nt < 3; ++nt) {
                    const int g  = nt * 96 + 8 * wj + (lane >> 2);
                    const int k0 = kt * 16 + (lane & 3) * 2;
                    const float* p = w_ih + (size_t)g * H_ + k0;
                    uint2 v;
                    v.x = pack_h2(__float2half_rn(p[0]), __float2half_rn(p[1]));
                    v.y = pack_h2(__float2half_rn(p[8]), __float2half_rn(p[9]));
                    wpIh[(wj * 18 + kt * 3 + nt) * 32 + lane] = v;
                }
        }
        // combined biases: [0:96) r, [96:192) z, [192:288) b_in, [288:384) b_hn
        if (tid < 96) {
            bias_s[tid]       = b_ih[tid]       + b_hh[tid];
            bias_s[96 + tid]  = b_ih[96 + tid]  + b_hh[96 + tid];
            bias_s[192 + tid] = b_ih[192 + tid];
            bias_s[288 + tid] = b_hh[192 + tid];
        }
    }

    const int crow = lane >> 2;
    const int jc   = 8 * wj + 2 * (lane & 3);
    const int rbase = mg * 16 + crow;

    // bias regs for !FUSED
    float bcr0 = 0, bcr1 = 0, bcz0 = 0, bcz1 = 0, bin0 = 0, bin1 = 0, bhn0 = 0, bhn1 = 0;
    if constexpr (!FUSED) {
        bcr0 = b_ih[jc]       + b_hh[jc];
        bcr1 = b_ih[jc + 1]   + b_hh[jc + 1];
        bcz0 = b_ih[96 + jc]  + b_hh[96 + jc];
        bcz1 = b_ih[97 + jc]  + b_hh[97 + jc];
        bin0 = b_ih[192 + jc];
        bin1 = b_ih[193 + jc];
        bhn0 = b_hh[192 + jc];
        bhn1 = b_hh[193 + jc];
    }

    // --- init h state ---
    float hold[4];
#pragma unroll
    for (int rh = 0; rh < 2; ++rh) {
        const int row = rbase + rh * 8;
        const float2 v = *(const float2*)&h0[(size_t)(b0 + row) * H_ + jc];
        hold[rh * 2]     = v.x;
        hold[rh * 2 + 1] = v.y;
        *(uint32_t*)&hb[0 * 32 * HP2 + row * HP2 + jc] =
            pack_h2(__float2half_rn(v.x), __float2half_rn(v.y));
    }

    // --- cp.async mapping (per m-group: 192 threads load the group's 16 rows)
    const int gidx    = tid - mg * 384;
    const bool cpon   = (gidx < 192);
    const int cprow   = mg * 16 + gidx / 12;
    const int cpchunk = gidx - (gidx / 12) * 12;
    const uint32_t xbS = (uint32_t)__cvta_generic_to_shared(xb)
                       + (uint32_t)(cprow * HP2 * 2 + cpchunk * 16);
    const uint32_t* xsrc0 = nullptr;
    constexpr uint32_t BUFB = (uint32_t)(32 * HP2 * 2);
    if constexpr (FUSED) {
        if (cpon) {
            xsrc0 = xg + (size_t)(b0 + cprow) * HW + cpchunk * 4;
            cpasync16(xbS, xsrc0);                           // x(0) -> slot0
            cpasync16(xbS + BUFB, xsrc0 + (size_t)B_ * HW);  // x(1) -> slot1
            cpasync_commit();
            cpasync_wait0();
        }
    }
    __syncthreads();

    // ldmatrix per-lane offsets
    const int arow = (lane & 7) + ((lane >> 3) & 1) * 8;
    const int acol = ((lane >> 4) & 1) * 8;
    const uint32_t lofs = (uint32_t)(((mg * 16 + arow) * HP2 + acol) * 2);
    const uint32_t hBase = (uint32_t)__cvta_generic_to_shared(hb) + lofs;
    const uint32_t xBase = (uint32_t)__cvta_generic_to_shared(xb) + lofs;

    const uint32_t wpIhS = (uint32_t)__cvta_generic_to_shared(wpIh)
                         + (uint32_t)(((wj * 18) * 32 + lane) * 8);
    const uint32_t biasS = (uint32_t)__cvta_generic_to_shared(bias_s);
    const uint32_t combRS = biasS + (uint32_t)(jc * 4);
    const uint32_t bhnS   = combRS + 288 * 4;

    const int barId = 1 + mg;

    float c[3][4], cx[4];
    float g2[3][4], g2x[4];

    if constexpr (FUSED) {
        // prologue: gi(0) -> c, gi(1) -> g2
        const float2 cr = lds2f(combRS);
        const float2 cz = lds2f(combRS + 96 * 4);
        const float2 bn = lds2f(combRS + 192 * 4);
        xgemm2(xBase, xBase + BUFB, wpIhS, cr, cz, bn, c, cx, g2, g2x);

        for (int tt = 0; tt + 1 < T_; tt += 2) {
            // ---- even step tt (accumulators c/cx; hb phase 0 -> 1) ----
            barg(barId);
            if (cpon) {
                const int a = (tt + 2 < T_) ? (tt + 2) : (T_ - 1);
                const int b = (tt + 3 < T_) ? (tt + 3) : (T_ - 1);
                cpasync16(xbS, xsrc0 + (size_t)a * B_ * HW);
                cpasync16(xbS + BUFB, xsrc0 + (size_t)b * B_ * HW);
                cpasync_commit();
            }
            hgemm(hBase, bhi, c);
            {
                const float2 bhn2 = lds2f(bhnS);
                elem_store(c, cx, hold, bhn2, rbase, jc, b0, tt,
                           hb + 32 * HP2, outg);
            }

            // ---- odd step tt+1 (accumulators g2/g2x; hb phase 1 -> 0) ----
            if (cpon) cpasync_wait0();
            barg(barId);
            hgemm(hBase + BUFB, bhi, g2);
            {
                const float2 bhn2 = lds2f(bhnS);
                elem_store(g2, g2x, hold, bhn2, rbase, jc, b0, tt + 1,
                           hb, outg);
            }
            // double x-GEMM: gi(tt+2) -> c, gi(tt+3) -> g2
            {
                const float2 cr2 = lds2f(combRS);
                const float2 cz2 = lds2f(combRS + 96 * 4);
                const float2 bn2 = lds2f(combRS + 192 * 4);
                xgemm2(xBase, xBase + BUFB, wpIhS, cr2, cz2, bn2, c, cx, g2, g2x);
            }
        }
        // ---- final even step t = T_-1 ----
        barg(barId);
        hgemm(hBase, bhi, c);
        {
            const float2 bhn2 = lds2f(bhnS);
            elem_store(c, cx, hold, bhn2, rbase, jc, b0, T_ - 1,
                       hb + 32 * HP2, outg);
        }
    } else {
        for (int t = 0; t < T_; ++t) {
            barg(barId);
#pragma unroll
            for (int q = 0; q < 4; ++q) {
                const bool od = q & 1;
                c[0][q] = od ? bcr1 : bcr0;
                c[1][q] = od ? bcz1 : bcz0;
                c[2][q] = 0.f;
                cx[q]   = od ? bin1 : bin0;
            }
            const uint32_t aH = hBase + (uint32_t)(t & 1) * BUFB;
            hgemm(aH, bhi, c);
            elem_store(c, cx, hold, make_float2(bhn0, bhn1), rbase, jc, b0, t,
                       hb + (uint32_t)((t & 1) ^ 1) * 32 * HP2, outg);
        }
    }
}

// ---------------------------------------------------------------------------
// fc1 (fp32, tiny)
// ---------------------------------------------------------------------------
__global__ void __launch_bounds__(256, 1)
fc1_kernel(const float* __restrict__ z, const float* __restrict__ c,
           const float* __restrict__ w, const float* __restrict__ bias,
           float* __restrict__ h0out)
{
    extern __shared__ float sm[];
    float* wc_s = sm;
    float* xc_s = wc_s + KC * NFCP;

    const int tid = threadIdx.x;
    const int cx  = tid & 31;
    const int ry  = tid >> 5;
    const int b0  = blockIdx.x * NB_;

    float acc[4][12];
#pragma unroll
    for (int m = 0; m < 4; ++m)
#pragma unroll
        for (int i = 0; i < 12; ++i) acc[m][i] = 0.f;

    for (int kc = 0; kc < KIN; kc += KC) {
        for (int idx = tid; idx < NFC * KC; idx += 256) {
            int g = idx / KC, kk = idx - g * KC;
            wc_s[kk * NFCP + g] = w[(size_t)g * KIN + kc + kk];
        }
        for (int idx = tid; idx < NB_ * KC; idx += 256) {
            int r = idx / KC, kk = idx - r * KC;
            int k = kc + kk;
            float v = (k < 256) ? z[(size_t)(b0 + r) * 256 + k]
                                : c[(size_t)(b0 + r) * 256 + (k - 256)];
            xc_s[kk * HPf + r] = v;
        }
        __syncthreads();
#pragma unroll 4
        for (int kk = 0; kk < KC; ++kk) {
            const float a0 = xc_s[kk * HPf + ry +  0];
            const float a1 = xc_s[kk * HPf + ry +  8];
            const float a2 = xc_s[kk * HPf + ry + 16];
            const float a3 = xc_s[kk * HPf + ry + 24];
            const float* wr = wc_s + kk * NFCP + cx;
#pragma unroll
            for (int i = 0; i < 12; ++i) {
                const float wv = wr[32 * i];
                acc[0][i] = fmaf(a0, wv, acc[0][i]);
                acc[1][i] = fmaf(a1, wv, acc[1][i]);
                acc[2][i] = fmaf(a2, wv, acc[2][i]);
                acc[3][i] = fmaf(a3, wv, acc[3][i]);
            }
        }
        __syncthreads();
    }

#pragma unroll
    for (int m = 0; m < 4; ++m) {
        const int r = b0 + ry + 8 * m;
#pragma unroll
        for (int i = 0; i < 12; ++i) {
            const int g = cx + 32 * i;
            float v = acc[m][i] + bias[g];
            v = (v >= 0.f) ? v : 0.2f * v;
            h0out[(size_t)r * NFC + g] = v;
        }
    }
}

// ---------------------------------------------------------------------------
// Transpose: packed fp16 [T,B,HW] -> fp32 [B,H,T]. Coalesced both sides.
// ---------------------------------------------------------------------------
__global__ void __launch_bounds__(256)
transpose16_kernel(const uint32_t* __restrict__ in, float* __restrict__ outp)
{
    __shared__ uint32_t tile[32][49];
    const int b  = blockIdx.y;
    const int t0 = blockIdx.x * 32;
    const int tid = threadIdx.x;

#pragma unroll
    for (int i = 0; i < 6; ++i) {
        const int idx = tid + i * 256;      // 0..1535 = 32 t x 48 words
        const int tt = idx / 48, jw = idx - (idx / 48) * 48;
        const int t = t0 + tt;
        if (t < T_) tile[tt][jw] = in[((size_t)t * B_ + b) * HW + jw];
    }
    __syncthreads();

#pragma unroll
    for (int i = 0; i < 12; ++i) {
        const int idx = tid + i * 256;      // 0..3071 = 96 j x 32 t
        const int j = idx >> 5, tt = idx & 31;
        const int t = t0 + tt;
        if (t < T_) {
            const uint32_t wv = tile[tt][j >> 1];
            const unsigned short hbits = (j & 1) ? (unsigned short)(wv >> 16)
                                                 : (unsigned short)(wv & 0xffffu);
            outp[((size_t)b * H_ + j) * T_ + t] = __half2float(__ushort_as_half(hbits));
        }
    }
}

// ---------------------------------------------------------------------------
extern "C" void kernel_launch(void* const* d_in, const int* in_sizes, int n_in,
                              void* d_out, int out_size)
{
    const float* z     = (const float*)d_in[0];
    const float* c     = (const float*)d_in[1];
    const float* fc1_w = (const float*)d_in[2];
    const float* fc1_b = (const float*)d_in[3];
    const float* w_ih  = (const float*)d_in[4];
    const float* w_hh  = (const float*)d_in[5];
    const float* b_ih  = (const float*)d_in[6];
    const float* b_hh  = (const float*)d_in[7];
    float* out = (float*)d_out;

    uint32_t *xA, *xB;
    float *h0Buf;
    cudaGetSymbolAddress((void**)&xA,    g_x16A);
    cudaGetSymbolAddress((void**)&xB,    g_x16B);
    cudaGetSymbolAddress((void**)&h0Buf, g_h0);

    constexpr int NFI = 12 * 18 * 32;
    const size_t smF = (size_t)NFI * 8
                     + (size_t)(4 * 32 * HP2) * sizeof(__half)
                     + (size_t)384 * sizeof(float);             // 83,456 B
    const size_t sm0 = (size_t)(4 * 32 * HP2) * sizeof(__half); // 26,624 B
    const size_t fcSm = (size_t)(KC * NFCP + KC * HPf) * sizeof(float);

    cudaFuncSetAttribute((const void*)scanF<false>, cudaFuncAttributeMaxDynamicSharedMemorySize, (int)sm0);
    cudaFuncSetAttribute((const void*)scanF<true>,  cudaFuncAttributeMaxDynamicSharedMemorySize, (int)smF);
    cudaFuncSetAttribute((const void*)fc1_kernel,   cudaFuncAttributeMaxDynamicSharedMemorySize, (int)fcSm);

    const int nblk = B_ / NB_;  // 128

    fc1_kernel<<<nblk, 256, fcSm>>>(z, c, fc1_w, fc1_b, h0Buf);

    // layer 0: input zeros -> fp16 activations into xA
    scanF<false><<<nblk, THR, sm0>>>(w_hh, b_hh, nullptr, b_ih,
                                     h0Buf, nullptr, xA);

    // layer 1: xA -> xB
    scanF<true><<<nblk, THR, smF>>>(w_hh + 1 * (size_t)G_ * H_, b_hh + 1 * G_,
                                    w_ih + 1 * (size_t)G_ * H_, b_ih + 1 * G_,
                                    h0Buf + 1 * (size_t)B_ * H_, xA, xB);
    // layer 2: xB -> xA
    scanF<true><<<nblk, THR, smF>>>(w_hh + 2 * (size_t)G_ * H_, b_hh + 2 * G_,
                                    w_ih + 2 * (size_t)G_ * H_, b_ih + 2 * G_,
                                    h0Buf + 2 * (size_t)B_ * H_, xB, xA);
    // layer 3: xA -> xB (packed fp16, coalesced)
    scanF<true><<<nblk, THR, smF>>>(w_hh + 3 * (size_t)G_ * H_, b_hh + 3 * G_,
                                    w_ih + 3 * (size_t)G_ * H_, b_ih + 3 * G_,
                                    h0Buf + 3 * (size_t)B_ * H_, xA, xB);

    // transpose fp16 [T,B,H] -> fp32 [B,H,T]
    transpose16_kernel<<<dim3(8, B_), 256>>>(xB, out);
}